// round 1
// baseline (speedup 1.0000x reference)
#include <cuda_runtime.h>
#include <math.h>

#define NN   100000
#define EE   220000
#define BB   4096
#define IND  75
#define HID  256
#define NH   8
#define CC   32
#define EDD  10
#define NL   4
#define TOTE (EE + NN)
#define BN_SCALE 0.9999950000375f
#define NEG_SLOPE 0.2f

// ---------------- scratch (device globals; no allocation allowed) ----------------
__device__ float g_h[NN * HID];
__device__ float g_xl[NN * HID];
__device__ float g_xr[NN * HID];
__device__ float g_out[NN * HID];
__device__ float g_elog[(size_t)TOTE * NH];
__device__ float g_max[NN * NH];
__device__ float g_den[NN * NH];
__device__ float g_meansum[EDD];
__device__ float g_epself[HID];
__device__ float g_g1[NN * (HID / 2)];
__device__ float g_gate[NN];
__device__ float g_gmax[BB];
__device__ float g_gden[BB];
__device__ float g_pooled[BB * HID];
__device__ float g_r1[BB * 256];
__device__ float g_r2[BB * 128];
__device__ float g_r3[BB * 64];

// buffer ids for the generic GEMM (device-side selection avoids cudaGetSymbolAddress)
#define ID_H      0
#define ID_XL     1
#define ID_XR     2
#define ID_G1     3
#define ID_POOLED 4
#define ID_R1     5
#define ID_R2     6
#define ID_R3     7

__device__ __forceinline__ float* bufsel(int id) {
    switch (id) {
        case ID_H:      return g_h;
        case ID_XL:     return g_xl;
        case ID_XR:     return g_xr;
        case ID_G1:     return g_g1;
        case ID_POOLED: return g_pooled;
        case ID_R1:     return g_r1;
        case ID_R2:     return g_r2;
        case ID_R3:     return g_r3;
    }
    return nullptr;
}

__device__ __forceinline__ void atomicMaxF(float* addr, float val) {
    int* ai = (int*)addr;
    int old = *ai;
    while (__int_as_float(old) < val) {
        int assumed = old;
        old = atomicCAS(ai, assumed, __float_as_int(val));
        if (old == assumed) break;
    }
}

// ---------------- small init kernels ----------------
__global__ void k_zero_small() {
    int i = threadIdx.x;
    if (i < EDD) g_meansum[i] = 0.f;
}

__global__ void k_init_layer() {
    int i = blockIdx.x * blockDim.x + threadIdx.x;
    if (i < NN * HID) g_out[i] = 0.f;
    if (i < NN * NH) { g_max[i] = -1e30f; g_den[i] = 0.f; }
}

__global__ void k_init_pool() {
    int i = blockIdx.x * blockDim.x + threadIdx.x;
    if (i < BB) { g_gmax[i] = -1e30f; g_gden[i] = 0.f; }
    if (i < BB * HID) g_pooled[i] = 0.f;
}

// ---------------- column mean of edge_attr (two-stage for precision) ----------------
__global__ void k_mean(const float* __restrict__ ea) {
    float loc[EDD];
#pragma unroll
    for (int k = 0; k < EDD; k++) loc[k] = 0.f;
    for (int e = blockIdx.x * blockDim.x + threadIdx.x; e < EE; e += gridDim.x * blockDim.x) {
#pragma unroll
        for (int k = 0; k < EDD; k++) loc[k] += ea[(size_t)e * EDD + k];
    }
#pragma unroll
    for (int k = 0; k < EDD; k++) {
        float v = loc[k];
#pragma unroll
        for (int o = 16; o; o >>= 1) v += __shfl_xor_sync(0xffffffffu, v, o);
        if ((threadIdx.x & 31) == 0) atomicAdd(&g_meansum[k], v);
    }
}

// ep_self = mean(edge_attr) @ We_i   (one 256-vector per layer)
__global__ void k_epself(const float* __restrict__ We) {
    int j = threadIdx.x;  // 256 threads
    const float invE = 1.f / (float)EE;
    float s = 0.f;
#pragma unroll
    for (int k = 0; k < EDD; k++) s += g_meansum[k] * invE * We[k * HID + j];
    g_epself[j] = s;
}

// ---------------- generic fp32 GEMM: C = act((A@B + bias) * scale) ----------------
// 64x64 tile, BK=16, 256 threads, 4x4 micro-tile
__global__ void k_gemm(const float* __restrict__ Aext, int a_id,
                       const float* __restrict__ B, const float* __restrict__ bias,
                       int c_id, int M, int K, int Nc, float scale, int act) {
    __shared__ float As[16][65];
    __shared__ float Bs[16][65];
    const float* A = (a_id < 0) ? Aext : bufsel(a_id);
    float* Cp = bufsel(c_id);

    int t = threadIdx.x;
    int tx = t & 15, ty = t >> 4;
    int n0 = blockIdx.x * 64, m0 = blockIdx.y * 64;
    float acc[4][4] = {};

    for (int kk = 0; kk < K; kk += 16) {
#pragma unroll
        for (int j = 0; j < 4; j++) {
            int idx = t + j * 256;
            int m = idx >> 4, k = idx & 15;
            int gm = m0 + m, gk = kk + k;
            As[k][m] = (gm < M && gk < K) ? A[(size_t)gm * K + gk] : 0.f;
        }
#pragma unroll
        for (int j = 0; j < 4; j++) {
            int idx = t + j * 256;
            int k = idx >> 6, n = idx & 63;
            int gk = kk + k;
            Bs[k][n] = (gk < K) ? B[(size_t)gk * Nc + n0 + n] : 0.f;
        }
        __syncthreads();
#pragma unroll
        for (int k = 0; k < 16; k++) {
            float a[4], b[4];
#pragma unroll
            for (int i = 0; i < 4; i++) a[i] = As[k][ty + 16 * i];
#pragma unroll
            for (int j = 0; j < 4; j++) b[j] = Bs[k][tx + 16 * j];
#pragma unroll
            for (int i = 0; i < 4; i++)
#pragma unroll
                for (int j = 0; j < 4; j++) acc[i][j] += a[i] * b[j];
        }
        __syncthreads();
    }
#pragma unroll
    for (int i = 0; i < 4; i++) {
        int gm = m0 + ty + 16 * i;
        if (gm >= M) continue;
#pragma unroll
        for (int j = 0; j < 4; j++) {
            int gn = n0 + tx + 16 * j;
            float v = acc[i][j];
            if (bias) v += bias[gn];
            v *= scale;
            if (act == 1) v = v > 0.f ? v : 0.f;
            else if (act == 2) v = v > 0.f ? v : expm1f(v);
            Cp[(size_t)gm * Nc + gn] = v;
        }
    }
}

// ---------------- GATv2 edge logits + segment max ----------------
__global__ void k_logits(const int* __restrict__ ei, const float* __restrict__ ea,
                         const float* __restrict__ We, const float* __restrict__ att) {
    __shared__ float sWe[EDD * HID];
    __shared__ float satt[HID];
    __shared__ float sep[HID];
    for (int i = threadIdx.x; i < EDD * HID; i += blockDim.x) sWe[i] = We[i];
    for (int i = threadIdx.x; i < HID; i += blockDim.x) { satt[i] = att[i]; sep[i] = g_epself[i]; }
    __syncthreads();

    int lane = threadIdx.x & 31;
    int warp = (blockIdx.x * blockDim.x + threadIdx.x) >> 5;
    int nwarps = (gridDim.x * blockDim.x) >> 5;

    for (int e = warp; e < TOTE; e += nwarps) {
        int src, tgt;
        float eav = 0.f;
        bool slf = (e >= EE);
        if (slf) { src = e - EE; tgt = src; }
        else {
            src = ei[e]; tgt = ei[EE + e];
            if (lane < EDD) eav = ea[(size_t)e * EDD + lane];
        }
        const float* xlr = g_xl + (size_t)src * HID;
        const float* xrr = g_xr + (size_t)tgt * HID;
#pragma unroll
        for (int hh = 0; hh < NH; hh++) {
            int cc = hh * CC + lane;
            float ep;
            if (slf) ep = sep[cc];
            else {
                ep = 0.f;
#pragma unroll
                for (int k = 0; k < EDD; k++)
                    ep += __shfl_sync(0xffffffffu, eav, k) * sWe[k * HID + cc];
            }
            float s = xlr[cc] + xrr[cc] + ep;
            s = s > 0.f ? s : NEG_SLOPE * s;
            float v = s * satt[cc];
#pragma unroll
            for (int o = 16; o; o >>= 1) v += __shfl_xor_sync(0xffffffffu, v, o);
            if (lane == hh) {
                g_elog[(size_t)e * NH + hh] = v;
                atomicMaxF(&g_max[tgt * NH + hh], v);
            }
        }
    }
}

// exp(logit - max) and segment denominator
__global__ void k_expnorm(const int* __restrict__ ei) {
    int idx = blockIdx.x * blockDim.x + threadIdx.x;
    if (idx >= TOTE * NH) return;
    int e = idx >> 3, hh = idx & 7;
    int tgt = (e < EE) ? ei[EE + e] : (e - EE);
    float v = __expf(g_elog[idx] - g_max[tgt * NH + hh]);
    g_elog[idx] = v;
    atomicAdd(&g_den[tgt * NH + hh], v);
}

// out[tgt] += alpha * xl[src]
__global__ void k_agg(const int* __restrict__ ei) {
    int lane = threadIdx.x & 31;
    int warp = (blockIdx.x * blockDim.x + threadIdx.x) >> 5;
    int nwarps = (gridDim.x * blockDim.x) >> 5;
    for (int e = warp; e < TOTE; e += nwarps) {
        int src, tgt;
        if (e >= EE) { src = e - EE; tgt = src; }
        else { src = ei[e]; tgt = ei[EE + e]; }
        float num = 0.f, den = 0.f;
        if (lane < NH) {
            num = g_elog[(size_t)e * NH + lane];
            den = g_den[tgt * NH + lane];
        }
        const float* xlr = g_xl + (size_t)src * HID;
        float* orow = g_out + (size_t)tgt * HID;
#pragma unroll
        for (int hh = 0; hh < NH; hh++) {
            float a = __shfl_sync(0xffffffffu, num, hh) /
                      (__shfl_sync(0xffffffffu, den, hh) + 1e-16f);
            atomicAdd(&orow[hh * CC + lane], a * xlr[hh * CC + lane]);
        }
    }
}

// h = elu((out + b_gat) * BN_S) + h
__global__ void k_update(const float* __restrict__ bgat) {
    int idx = blockIdx.x * blockDim.x + threadIdx.x;
    if (idx >= NN * HID) return;
    int col = idx & (HID - 1);
    float v = (g_out[idx] + bgat[col]) * BN_SCALE;
    v = v > 0.f ? v : expm1f(v);
    g_h[idx] = v + g_h[idx];
}

// gate = g1 @ Wg2 + bg2   (warp per node)
__global__ void k_gatedot(const float* __restrict__ Wg2, const float* __restrict__ bg2) {
    int lane = threadIdx.x & 31;
    int warp = (blockIdx.x * blockDim.x + threadIdx.x) >> 5;
    if (warp >= NN) return;
    float s = 0.f;
#pragma unroll
    for (int j = lane; j < 128; j += 32) s += g_g1[(size_t)warp * 128 + j] * Wg2[j];
#pragma unroll
    for (int o = 16; o; o >>= 1) s += __shfl_xor_sync(0xffffffffu, s, o);
    if (lane == 0) g_gate[warp] = s + bg2[0];
}

__global__ void k_gpool_max(const int* __restrict__ batch) {
    int n = blockIdx.x * blockDim.x + threadIdx.x;
    if (n < NN) atomicMaxF(&g_gmax[batch[n]], g_gate[n]);
}

__global__ void k_gpool_exp(const int* __restrict__ batch) {
    int n = blockIdx.x * blockDim.x + threadIdx.x;
    if (n >= NN) return;
    int b = batch[n];
    float v = __expf(g_gate[n] - g_gmax[b]);
    g_gate[n] = v;
    atomicAdd(&g_gden[b], v);
}

__global__ void k_pool(const int* __restrict__ batch) {
    int lane = threadIdx.x & 31;
    int warp = (blockIdx.x * blockDim.x + threadIdx.x) >> 5;
    if (warp >= NN) return;
    int b = batch[warp];
    float a = g_gate[warp] / (g_gden[b] + 1e-16f);
    const float* hr = g_h + (size_t)warp * HID;
    float* pr = g_pooled + (size_t)b * HID;
#pragma unroll
    for (int j = lane; j < HID; j += 32) atomicAdd(&pr[j], a * hr[j]);
}

__global__ void k_final(const float* __restrict__ W4, const float* __restrict__ b4,
                        float* __restrict__ out) {
    int b = blockIdx.x * blockDim.x + threadIdx.x;
    if (b >= BB) return;
    float s = b4[0];
#pragma unroll
    for (int k = 0; k < 64; k++) s += g_r3[b * 64 + k] * W4[k];
    out[b] = s;
}

// ---------------- host orchestration ----------------
extern "C" void kernel_launch(void* const* d_in, const int* in_sizes, int n_in,
                              void* d_out, int out_size) {
    const float* x     = (const float*)d_in[0];
    const int*   ei    = (const int*)  d_in[1];
    const float* ea    = (const float*)d_in[2];
    const int*   batch = (const int*)  d_in[3];
    const float* W_in  = (const float*)d_in[4];
    const float* b_in  = (const float*)d_in[5];
    const float* Wl    = (const float*)d_in[6];
    const float* Wr    = (const float*)d_in[7];
    const float* We    = (const float*)d_in[8];
    const float* att   = (const float*)d_in[9];
    const float* b_gat = (const float*)d_in[10];
    const float* Wg1   = (const float*)d_in[11];
    const float* bg1   = (const float*)d_in[12];
    const float* Wg2   = (const float*)d_in[13];
    const float* bg2   = (const float*)d_in[14];
    const float* W1    = (const float*)d_in[15];
    const float* b1    = (const float*)d_in[16];
    const float* W2    = (const float*)d_in[17];
    const float* b2    = (const float*)d_in[18];
    const float* W3    = (const float*)d_in[19];
    const float* b3    = (const float*)d_in[20];
    const float* W4    = (const float*)d_in[21];
    const float* b4    = (const float*)d_in[22];
    float* out = (float*)d_out;

    const int MB = (NN + 63) / 64;  // 1563 row tiles for node GEMMs
    dim3 thr(256);

    // edge_attr column mean
    k_zero_small<<<1, 32>>>();
    k_mean<<<256, 256>>>(ea);

    // input projection: h = elu((x @ W_in + b_in) * BN_S)
    k_gemm<<<dim3(HID / 64, MB), thr>>>(x, -1, W_in, b_in, ID_H, NN, IND, HID, BN_SCALE, 2);

    for (int i = 0; i < NL; i++) {
        const float* Wli = Wl + (size_t)i * HID * HID;
        const float* Wri = Wr + (size_t)i * HID * HID;
        const float* Wei = We + (size_t)i * EDD * HID;
        const float* ati = att + (size_t)i * NH * CC;
        const float* bgi = b_gat + (size_t)i * HID;

        k_gemm<<<dim3(HID / 64, MB), thr>>>(nullptr, ID_H, Wli, nullptr, ID_XL, NN, HID, HID, 1.f, 0);
        k_gemm<<<dim3(HID / 64, MB), thr>>>(nullptr, ID_H, Wri, nullptr, ID_XR, NN, HID, HID, 1.f, 0);
        k_epself<<<1, HID>>>(Wei);
        k_init_layer<<<(NN * HID + 255) / 256, thr>>>();
        k_logits<<<8192, thr>>>(ei, ea, Wei, ati);
        k_expnorm<<<(TOTE * NH + 255) / 256, thr>>>(ei);
        k_agg<<<8192, thr>>>(ei);
        k_update<<<(NN * HID + 255) / 256, thr>>>(bgi);
    }

    // global attention pooling
    k_gemm<<<dim3(128 / 64, MB), thr>>>(nullptr, ID_H, Wg1, bg1, ID_G1, NN, HID, 128, 1.f, 1);
    k_gatedot<<<(NN * 32 + 255) / 256, thr>>>(Wg2, bg2);
    k_init_pool<<<(BB * HID + 255) / 256, thr>>>();
    k_gpool_max<<<(NN + 255) / 256, thr>>>(batch);
    k_gpool_exp<<<(NN + 255) / 256, thr>>>(batch);
    k_pool<<<(NN * 32 + 255) / 256, thr>>>(batch);

    // readout MLP
    k_gemm<<<dim3(256 / 64, BB / 64), thr>>>(nullptr, ID_POOLED, W1, b1, ID_R1, BB, HID, 256, BN_SCALE, 1);
    k_gemm<<<dim3(128 / 64, BB / 64), thr>>>(nullptr, ID_R1, W2, b2, ID_R2, BB, 256, 128, BN_SCALE, 1);
    k_gemm<<<dim3(64 / 64, BB / 64), thr>>>(nullptr, ID_R2, W3, b3, ID_R3, BB, 128, 64, 1.f, 1);
    k_final<<<(BB + 255) / 256, thr>>>(W4, b4, out);
}

// round 4
// speedup vs baseline: 1.7556x; 1.7556x over previous
#include <cuda_runtime.h>
#include <math.h>
#include <stdint.h>

#define NN   100000
#define EE   220000
#define BB   4096
#define IND  75
#define HID  256
#define NH   8
#define CC   32
#define EDD  10
#define NL   4
#define TOTE (EE + NN)
#define BN_SCALE 0.9999950000375f
#define NEG_SLOPE 0.2f

// ---------------- scratch (device globals; no allocation allowed) ----------------
__device__ float g_h[NN * HID];
__device__ float g_xl[NN * HID];
__device__ float g_xr[NN * HID];
__device__ float g_out[NN * HID];
__device__ float g_elog[(size_t)TOTE * NH];
__device__ float g_max[NN * NH];
__device__ float g_den[NN * NH];
__device__ float g_meansum[EDD];
__device__ float g_epself[HID];
__device__ float g_g1[NN * (HID / 2)];
__device__ float g_gate[NN];
__device__ float g_gmax[BB];
__device__ float g_gden[BB];
__device__ float g_pooled[BB * HID];
__device__ float g_r1[BB * 256];
__device__ float g_r2[BB * 128];
__device__ float g_r3[BB * 64];
__device__ float g_wt[600000];   // transposed tf32-rounded weights [N x Kpad]

#define ID_H      0
#define ID_XL     1
#define ID_XR     2
#define ID_G1     3
#define ID_POOLED 4
#define ID_R1     5
#define ID_R2     6
#define ID_R3     7

// g_wt offsets
#define WT_WIN   0
#define WT_WL(i) (24576 + (i) * 65536)
#define WT_WR(i) (24576 + (4 + (i)) * 65536)
#define WT_WG1   (24576 + 8 * 65536)

__device__ __forceinline__ float* bufsel(int id) {
    switch (id) {
        case ID_H:      return g_h;
        case ID_XL:     return g_xl;
        case ID_XR:     return g_xr;
        case ID_G1:     return g_g1;
        case ID_POOLED: return g_pooled;
        case ID_R1:     return g_r1;
        case ID_R2:     return g_r2;
        case ID_R3:     return g_r3;
    }
    return nullptr;
}

__device__ __forceinline__ void atomicMaxF(float* addr, float val) {
    int* ai = (int*)addr;
    int old = *ai;
    while (__int_as_float(old) < val) {
        int assumed = old;
        old = atomicCAS(ai, assumed, __float_as_int(val));
        if (old == assumed) break;
    }
}

__device__ __forceinline__ uint32_t rna_tf32(float f) {
    uint32_t u;
    asm("cvt.rna.tf32.f32 %0, %1;" : "=r"(u) : "f"(f));
    return u;
}

__device__ __forceinline__ void mma8(float* c, const uint32_t* a, const uint32_t* b) {
    asm volatile(
        "mma.sync.aligned.m16n8k8.row.col.f32.tf32.tf32.f32 "
        "{%0,%1,%2,%3}, {%4,%5,%6,%7}, {%8,%9}, {%0,%1,%2,%3};"
        : "+f"(c[0]), "+f"(c[1]), "+f"(c[2]), "+f"(c[3])
        : "r"(a[0]), "r"(a[1]), "r"(a[2]), "r"(a[3]), "r"(b[0]), "r"(b[1]));
}

// ---------------- weight transpose + tf32 round: dst[n*Kpad+k] = rna(W[k*N+n]) ----------------
__global__ void k_transpose(const float* __restrict__ W, int K, int N, int Kpad, int dstoff) {
    int idx = blockIdx.x * blockDim.x + threadIdx.x;
    if (idx >= N * Kpad) return;
    int n = idx / Kpad, k = idx % Kpad;
    float v = (k < K) ? W[(size_t)k * N + n] : 0.f;
    g_wt[dstoff + idx] = __uint_as_float(rna_tf32(v));
}

// ---------------- tf32 mma.sync GEMM ----------------
// C[M x Nc] = act((A[M x lda] @ Wt^T + bias) * scale); Wt = g_wt+bt_off as [Nc x ldb]
// block tile 128x128, BK=32, 256 threads (8 warps, each 32x64)
#define TSTRIDE 36
#define ABUFB   (128 * TSTRIDE * 4)          // 18432
#define TILEB   (2 * ABUFB)                  // As + Bs per buffer
__global__ void __launch_bounds__(256) k_mgemm(
        const float* __restrict__ Aext, int a_id, int bt_off,
        const float* __restrict__ bias, int c_id,
        int M, int lda, int KS, int ldb, int Nc, float scale, int act) {
    extern __shared__ char smc[];
    const float* A = (a_id < 0) ? Aext : bufsel(a_id);
    const float* Wt = g_wt + bt_off;
    float* C = bufsel(c_id);

    int tid = threadIdx.x, lane = tid & 31, wid = tid >> 5;
    int wm = wid & 3, wn = wid >> 2;          // warp tile: rows wm*32, cols wn*64
    int m0 = blockIdx.y * 128;
    int n0g = blockIdx.x * 128;

    int arow = tid >> 1, ahalf = tid & 1;     // A staging: 2 threads per row, 16 cols each
    const bool vec = ((lda & 3) == 0);

    uint32_t sbase;
    asm("{ .reg .u64 t; cvta.to.shared.u64 t, %1; cvt.u32.u64 %0, t; }" : "=r"(sbase) : "l"(smc));

    float pre[16];

    auto loadA_regs = [&](int kc) {
        int gm = m0 + arow;
        int k0 = kc * 32 + ahalf * 16;
        if (gm < M) {
            if (vec) {
#pragma unroll
                for (int i = 0; i < 4; i++) {
                    float4 t = *reinterpret_cast<const float4*>(A + (size_t)gm * lda + k0 + i * 4);
                    pre[i * 4 + 0] = t.x; pre[i * 4 + 1] = t.y;
                    pre[i * 4 + 2] = t.z; pre[i * 4 + 3] = t.w;
                }
            } else {
#pragma unroll
                for (int i = 0; i < 16; i++)
                    pre[i] = (k0 + i < lda) ? A[(size_t)gm * lda + k0 + i] : 0.f;
            }
        } else {
#pragma unroll
            for (int i = 0; i < 16; i++) pre[i] = 0.f;
        }
    };
    auto stsA = [&](int buf) {
        float* As = (float*)(smc + buf * TILEB);
#pragma unroll
        for (int i = 0; i < 4; i++) {
            uint32_t v[4];
#pragma unroll
            for (int e = 0; e < 4; e++) v[e] = rna_tf32(pre[i * 4 + e]);
            *reinterpret_cast<uint4*>(&As[arow * TSTRIDE + ahalf * 16 + i * 4]) =
                *reinterpret_cast<uint4*>(v);
        }
    };
    auto loadB = [&](int kc, int buf) {
        uint32_t bb = sbase + buf * TILEB + ABUFB;
#pragma unroll
        for (int j = 0; j < 4; j++) {
            int flat = tid + j * 256;          // 1024 chunks of 16B
            int n = flat >> 3, k4 = flat & 7;
            uint32_t dst = bb + n * (TSTRIDE * 4) + k4 * 16;
            const float* src = Wt + (size_t)(n0g + n) * ldb + kc * 32 + k4 * 4;
            asm volatile("cp.async.cg.shared.global [%0], [%1], 16;" :: "r"(dst), "l"(src) : "memory");
        }
    };

    float acc[2][8][4];
#pragma unroll
    for (int mi = 0; mi < 2; mi++)
#pragma unroll
        for (int ni = 0; ni < 8; ni++)
#pragma unroll
            for (int e = 0; e < 4; e++) acc[mi][ni][e] = 0.f;

    loadA_regs(0);
    loadB(0, 0);
    stsA(0);
    asm volatile("cp.async.commit_group;\n\tcp.async.wait_group 0;" ::: "memory");
    __syncthreads();

    for (int kc = 0; kc < KS; kc++) {
        int cur = kc & 1, nxt = 1 - cur;
        if (kc + 1 < KS) {
            loadA_regs(kc + 1);
            loadB(kc + 1, nxt);
            asm volatile("cp.async.commit_group;" ::: "memory");
        }
        const float* As = (const float*)(smc + cur * TILEB);
        const float* Bs = (const float*)(smc + cur * TILEB + ABUFB);
        const uint32_t* Asu = (const uint32_t*)As;
        const uint32_t* Bsu = (const uint32_t*)Bs;
        int lq = lane >> 2, lr = lane & 3;
#pragma unroll
        for (int kt = 0; kt < 4; kt++) {
            int k8 = kt * 8;
            uint32_t afr[2][4];
#pragma unroll
            for (int mi = 0; mi < 2; mi++) {
                int rb = wm * 32 + mi * 16;
                afr[mi][0] = Asu[(rb + lq) * TSTRIDE + k8 + lr];
                afr[mi][1] = Asu[(rb + 8 + lq) * TSTRIDE + k8 + lr];
                afr[mi][2] = Asu[(rb + lq) * TSTRIDE + k8 + lr + 4];
                afr[mi][3] = Asu[(rb + 8 + lq) * TSTRIDE + k8 + lr + 4];
            }
            uint32_t bfr[8][2];
#pragma unroll
            for (int ni = 0; ni < 8; ni++) {
                int nb = wn * 64 + ni * 8;
                bfr[ni][0] = Bsu[(nb + lq) * TSTRIDE + k8 + lr];
                bfr[ni][1] = Bsu[(nb + lq) * TSTRIDE + k8 + lr + 4];
            }
#pragma unroll
            for (int mi = 0; mi < 2; mi++)
#pragma unroll
                for (int ni = 0; ni < 8; ni++)
                    mma8(acc[mi][ni], afr[mi], bfr[ni]);
        }
        if (kc + 1 < KS) {
            stsA(nxt);
            asm volatile("cp.async.wait_group 0;" ::: "memory");
            __syncthreads();
        }
    }

    // epilogue
    int lq = lane >> 2, lr = lane & 3;
#pragma unroll
    for (int mi = 0; mi < 2; mi++) {
        int r0 = m0 + wm * 32 + mi * 16 + lq;
#pragma unroll
        for (int half = 0; half < 2; half++) {
            int gr = r0 + half * 8;
            if (gr >= M) continue;
#pragma unroll
            for (int ni = 0; ni < 8; ni++) {
                int gc = n0g + wn * 64 + ni * 8 + 2 * lr;
                float v0 = acc[mi][ni][half * 2 + 0];
                float v1 = acc[mi][ni][half * 2 + 1];
                if (bias) { v0 += __ldg(&bias[gc]); v1 += __ldg(&bias[gc + 1]); }
                v0 *= scale; v1 *= scale;
                if (act == 1) { v0 = v0 > 0.f ? v0 : 0.f; v1 = v1 > 0.f ? v1 : 0.f; }
                else if (act == 2) {
                    v0 = v0 > 0.f ? v0 : expm1f(v0);
                    v1 = v1 > 0.f ? v1 : expm1f(v1);
                }
                *reinterpret_cast<float2*>(C + (size_t)gr * Nc + gc) = make_float2(v0, v1);
            }
        }
    }
}

// ---------------- small init kernels ----------------
__global__ void k_zero_small() {
    int i = threadIdx.x;
    if (i < EDD) g_meansum[i] = 0.f;
}

__global__ void k_init_layer() {
    int i = blockIdx.x * blockDim.x + threadIdx.x;
    if (i < NN * HID) g_out[i] = 0.f;
    if (i < NN * NH) { g_max[i] = -1e30f; g_den[i] = 0.f; }
}

__global__ void k_init_pool() {
    int i = blockIdx.x * blockDim.x + threadIdx.x;
    if (i < BB) { g_gmax[i] = -1e30f; g_gden[i] = 0.f; }
    if (i < BB * HID) g_pooled[i] = 0.f;
}

// ---------------- column mean of edge_attr ----------------
__global__ void k_mean(const float* __restrict__ ea) {
    float loc[EDD];
#pragma unroll
    for (int k = 0; k < EDD; k++) loc[k] = 0.f;
    for (int e = blockIdx.x * blockDim.x + threadIdx.x; e < EE; e += gridDim.x * blockDim.x) {
#pragma unroll
        for (int k = 0; k < EDD; k++) loc[k] += ea[(size_t)e * EDD + k];
    }
#pragma unroll
    for (int k = 0; k < EDD; k++) {
        float v = loc[k];
#pragma unroll
        for (int o = 16; o; o >>= 1) v += __shfl_xor_sync(0xffffffffu, v, o);
        if ((threadIdx.x & 31) == 0) atomicAdd(&g_meansum[k], v);
    }
}

__global__ void k_epself(const float* __restrict__ We) {
    int j = threadIdx.x;
    const float invE = 1.f / (float)EE;
    float s = 0.f;
#pragma unroll
    for (int k = 0; k < EDD; k++) s += g_meansum[k] * invE * We[k * HID + j];
    g_epself[j] = s;
}

// ---------------- SIMT GEMM (small readout mats only) ----------------
__global__ void k_gemm(const float* __restrict__ Aext, int a_id,
                       const float* __restrict__ B, const float* __restrict__ bias,
                       int c_id, int M, int K, int Nc, float scale, int act) {
    __shared__ float As[16][65];
    __shared__ float Bs[16][65];
    const float* A = (a_id < 0) ? Aext : bufsel(a_id);
    float* Cp = bufsel(c_id);

    int t = threadIdx.x;
    int tx = t & 15, ty = t >> 4;
    int n0 = blockIdx.x * 64, m0 = blockIdx.y * 64;
    float acc[4][4] = {};

    for (int kk = 0; kk < K; kk += 16) {
#pragma unroll
        for (int j = 0; j < 4; j++) {
            int idx = t + j * 256;
            int m = idx >> 4, k = idx & 15;
            int gm = m0 + m, gk = kk + k;
            As[k][m] = (gm < M && gk < K) ? A[(size_t)gm * K + gk] : 0.f;
        }
#pragma unroll
        for (int j = 0; j < 4; j++) {
            int idx = t + j * 256;
            int k = idx >> 6, n = idx & 63;
            int gk = kk + k;
            Bs[k][n] = (gk < K) ? B[(size_t)gk * Nc + n0 + n] : 0.f;
        }
        __syncthreads();
#pragma unroll
        for (int k = 0; k < 16; k++) {
            float a[4], b[4];
#pragma unroll
            for (int i = 0; i < 4; i++) a[i] = As[k][ty + 16 * i];
#pragma unroll
            for (int j = 0; j < 4; j++) b[j] = Bs[k][tx + 16 * j];
#pragma unroll
            for (int i = 0; i < 4; i++)
#pragma unroll
                for (int j = 0; j < 4; j++) acc[i][j] += a[i] * b[j];
        }
        __syncthreads();
    }
#pragma unroll
    for (int i = 0; i < 4; i++) {
        int gm = m0 + ty + 16 * i;
        if (gm >= M) continue;
#pragma unroll
        for (int j = 0; j < 4; j++) {
            int gn = n0 + tx + 16 * j;
            float v = acc[i][j];
            if (bias) v += bias[gn];
            v *= scale;
            if (act == 1) v = v > 0.f ? v : 0.f;
            else if (act == 2) v = v > 0.f ? v : expm1f(v);
            Cp[(size_t)gm * Nc + gn] = v;
        }
    }
}

// ---------------- GATv2 edge logits + segment max ----------------
__global__ void k_logits(const int* __restrict__ ei, const float* __restrict__ ea,
                         const float* __restrict__ We, const float* __restrict__ att) {
    __shared__ float sWe[EDD * HID];
    __shared__ float satt[HID];
    __shared__ float sep[HID];
    for (int i = threadIdx.x; i < EDD * HID; i += blockDim.x) sWe[i] = We[i];
    for (int i = threadIdx.x; i < HID; i += blockDim.x) { satt[i] = att[i]; sep[i] = g_epself[i]; }
    __syncthreads();

    int lane = threadIdx.x & 31;
    int warp = (blockIdx.x * blockDim.x + threadIdx.x) >> 5;
    int nwarps = (gridDim.x * blockDim.x) >> 5;

    for (int e = warp; e < TOTE; e += nwarps) {
        int src, tgt;
        float eav = 0.f;
        bool slf = (e >= EE);
        if (slf) { src = e - EE; tgt = src; }
        else {
            src = ei[e]; tgt = ei[EE + e];
            if (lane < EDD) eav = ea[(size_t)e * EDD + lane];
        }
        const float* xlr = g_xl + (size_t)src * HID;
        const float* xrr = g_xr + (size_t)tgt * HID;
#pragma unroll
        for (int hh = 0; hh < NH; hh++) {
            int cc = hh * CC + lane;
            float ep;
            if (slf) ep = sep[cc];
            else {
                ep = 0.f;
#pragma unroll
                for (int k = 0; k < EDD; k++)
                    ep += __shfl_sync(0xffffffffu, eav, k) * sWe[k * HID + cc];
            }
            float s = xlr[cc] + xrr[cc] + ep;
            s = s > 0.f ? s : NEG_SLOPE * s;
            float v = s * satt[cc];
#pragma unroll
            for (int o = 16; o; o >>= 1) v += __shfl_xor_sync(0xffffffffu, v, o);
            if (lane == hh) {
                g_elog[(size_t)e * NH + hh] = v;
                atomicMaxF(&g_max[tgt * NH + hh], v);
            }
        }
    }
}

__global__ void k_expnorm(const int* __restrict__ ei) {
    int idx = blockIdx.x * blockDim.x + threadIdx.x;
    if (idx >= TOTE * NH) return;
    int e = idx >> 3, hh = idx & 7;
    int tgt = (e < EE) ? ei[EE + e] : (e - EE);
    float v = __expf(g_elog[idx] - g_max[tgt * NH + hh]);
    g_elog[idx] = v;
    atomicAdd(&g_den[tgt * NH + hh], v);
}

__global__ void k_agg(const int* __restrict__ ei) {
    int lane = threadIdx.x & 31;
    int warp = (blockIdx.x * blockDim.x + threadIdx.x) >> 5;
    int nwarps = (gridDim.x * blockDim.x) >> 5;
    for (int e = warp; e < TOTE; e += nwarps) {
        int src, tgt;
        if (e >= EE) { src = e - EE; tgt = src; }
        else { src = ei[e]; tgt = ei[EE + e]; }
        float num = 0.f, den = 0.f;
        if (lane < NH) {
            num = g_elog[(size_t)e * NH + lane];
            den = g_den[tgt * NH + lane];
        }
        const float* xlr = g_xl + (size_t)src * HID;
        float* orow = g_out + (size_t)tgt * HID;
#pragma unroll
        for (int hh = 0; hh < NH; hh++) {
            float a = __shfl_sync(0xffffffffu, num, hh) /
                      (__shfl_sync(0xffffffffu, den, hh) + 1e-16f);
            atomicAdd(&orow[hh * CC + lane], a * xlr[hh * CC + lane]);
        }
    }
}

__global__ void k_update(const float* __restrict__ bgat) {
    int idx = blockIdx.x * blockDim.x + threadIdx.x;
    if (idx >= NN * HID) return;
    int col = idx & (HID - 1);
    float v = (g_out[idx] + bgat[col]) * BN_SCALE;
    v = v > 0.f ? v : expm1f(v);
    g_h[idx] = v + g_h[idx];
}

__global__ void k_gatedot(const float* __restrict__ Wg2, const float* __restrict__ bg2) {
    int lane = threadIdx.x & 31;
    int warp = (blockIdx.x * blockDim.x + threadIdx.x) >> 5;
    if (warp >= NN) return;
    float s = 0.f;
#pragma unroll
    for (int j = lane; j < 128; j += 32) s += g_g1[(size_t)warp * 128 + j] * Wg2[j];
#pragma unroll
    for (int o = 16; o; o >>= 1) s += __shfl_xor_sync(0xffffffffu, s, o);
    if (lane == 0) g_gate[warp] = s + bg2[0];
}

__global__ void k_gpool_max(const int* __restrict__ batch) {
    int n = blockIdx.x * blockDim.x + threadIdx.x;
    if (n < NN) atomicMaxF(&g_gmax[batch[n]], g_gate[n]);
}

__global__ void k_gpool_exp(const int* __restrict__ batch) {
    int n = blockIdx.x * blockDim.x + threadIdx.x;
    if (n >= NN) return;
    int b = batch[n];
    float v = __expf(g_gate[n] - g_gmax[b]);
    g_gate[n] = v;
    atomicAdd(&g_gden[b], v);
}

__global__ void k_pool(const int* __restrict__ batch) {
    int lane = threadIdx.x & 31;
    int warp = (blockIdx.x * blockDim.x + threadIdx.x) >> 5;
    if (warp >= NN) return;
    int b = batch[warp];
    float a = g_gate[warp] / (g_gden[b] + 1e-16f);
    const float* hr = g_h + (size_t)warp * HID;
    float* pr = g_pooled + (size_t)b * HID;
#pragma unroll
    for (int j = lane; j < HID; j += 32) atomicAdd(&pr[j], a * hr[j]);
}

__global__ void k_final(const float* __restrict__ W4, const float* __restrict__ b4,
                        float* __restrict__ out) {
    int b = blockIdx.x * blockDim.x + threadIdx.x;
    if (b >= BB) return;
    float s = b4[0];
#pragma unroll
    for (int k = 0; k < 64; k++) s += g_r3[b * 64 + k] * W4[k];
    out[b] = s;
}

// ---------------- host orchestration ----------------
extern "C" void kernel_launch(void* const* d_in, const int* in_sizes, int n_in,
                              void* d_out, int out_size) {
    const float* x     = (const float*)d_in[0];
    const int*   ei    = (const int*)  d_in[1];
    const float* ea    = (const float*)d_in[2];
    const int*   batch = (const int*)  d_in[3];
    const float* W_in  = (const float*)d_in[4];
    const float* b_in  = (const float*)d_in[5];
    const float* Wl    = (const float*)d_in[6];
    const float* Wr    = (const float*)d_in[7];
    const float* We    = (const float*)d_in[8];
    const float* att   = (const float*)d_in[9];
    const float* b_gat = (const float*)d_in[10];
    const float* Wg1   = (const float*)d_in[11];
    const float* bg1   = (const float*)d_in[12];
    const float* Wg2   = (const float*)d_in[13];
    const float* bg2   = (const float*)d_in[14];
    const float* W1    = (const float*)d_in[15];
    const float* b1    = (const float*)d_in[16];
    const float* W2    = (const float*)d_in[17];
    const float* b2    = (const float*)d_in[18];
    const float* W3    = (const float*)d_in[19];
    const float* b3    = (const float*)d_in[20];
    const float* W4    = (const float*)d_in[21];
    const float* b4    = (const float*)d_in[22];
    float* out = (float*)d_out;

    const int SMEM = 2 * TILEB;  // 73728
    cudaFuncSetAttribute(k_mgemm, cudaFuncAttributeMaxDynamicSharedMemorySize, SMEM);

    const int MTB = (NN + 127) / 128;  // 782
    dim3 thr(256);

    // transpose + tf32-round all mma-GEMM weights into scratch
    k_transpose<<<(256 * 96 + 255) / 256, 256>>>(W_in, IND, HID, 96, WT_WIN);
    for (int i = 0; i < NL; i++) {
        k_transpose<<<(256 * 256 + 255) / 256, 256>>>(Wl + (size_t)i * 65536, HID, HID, 256, WT_WL(i));
        k_transpose<<<(256 * 256 + 255) / 256, 256>>>(Wr + (size_t)i * 65536, HID, HID, 256, WT_WR(i));
    }
    k_transpose<<<(128 * 256 + 255) / 256, 256>>>(Wg1, HID, 128, 256, WT_WG1);

    // edge_attr column mean
    k_zero_small<<<1, 32>>>();
    k_mean<<<256, 256>>>(ea);

    // input projection: h = elu((x @ W_in + b_in) * BN_S)
    k_mgemm<<<dim3(2, MTB), thr, SMEM>>>(x, -1, WT_WIN, b_in, ID_H, NN, IND, 3, 96, HID, BN_SCALE, 2);

    for (int i = 0; i < NL; i++) {
        const float* Wei = We + (size_t)i * EDD * HID;
        const float* ati = att + (size_t)i * NH * CC;
        const float* bgi = b_gat + (size_t)i * HID;

        k_mgemm<<<dim3(2, MTB), thr, SMEM>>>(nullptr, ID_H, WT_WL(i), nullptr, ID_XL, NN, HID, 8, 256, HID, 1.f, 0);
        k_mgemm<<<dim3(2, MTB), thr, SMEM>>>(nullptr, ID_H, WT_WR(i), nullptr, ID_XR, NN, HID, 8, 256, HID, 1.f, 0);
        k_epself<<<1, HID>>>(Wei);
        k_init_layer<<<(NN * HID + 255) / 256, thr>>>();
        k_logits<<<8192, thr>>>(ei, ea, Wei, ati);
        k_expnorm<<<(TOTE * NH + 255) / 256, thr>>>(ei);
        k_agg<<<8192, thr>>>(ei);
        k_update<<<(NN * HID + 255) / 256, thr>>>(bgi);
    }

    // global attention pooling
    k_mgemm<<<dim3(1, MTB), thr, SMEM>>>(nullptr, ID_H, WT_WG1, bg1, ID_G1, NN, HID, 8, 256, 128, 1.f, 1);
    k_gatedot<<<(NN * 32 + 255) / 256, thr>>>(Wg2, bg2);
    k_init_pool<<<(BB * HID + 255) / 256, thr>>>();
    k_gpool_max<<<(NN + 255) / 256, thr>>>(batch);
    k_gpool_exp<<<(NN + 255) / 256, thr>>>(batch);
    k_pool<<<(NN * 32 + 255) / 256, thr>>>(batch);

    // readout MLP (small; SIMT)
    k_gemm<<<dim3(256 / 64, BB / 64), thr>>>(nullptr, ID_POOLED, W1, b1, ID_R1, BB, HID, 256, BN_SCALE, 1);
    k_gemm<<<dim3(128 / 64, BB / 64), thr>>>(nullptr, ID_R1, W2, b2, ID_R2, BB, 256, 128, BN_SCALE, 1);
    k_gemm<<<dim3(64 / 64, BB / 64), thr>>>(nullptr, ID_R2, W3, b3, ID_R3, BB, 128, 64, 1.f, 1);
    k_final<<<(BB + 255) / 256, thr>>>(W4, b4, out);
}

// round 5
// speedup vs baseline: 1.9263x; 1.0972x over previous
#include <cuda_runtime.h>
#include <cuda_fp16.h>
#include <math.h>
#include <stdint.h>

#define NN   100000
#define EE   220000
#define BB   4096
#define IND  75
#define HID  256
#define NH   8
#define CC   32
#define EDD  10
#define NL   4
#define TOTE (EE + NN)
#define BN_SCALE 0.9999950000375f
#define NEG_SLOPE 0.2f

// ---------------- scratch (device globals; no allocation allowed) ----------------
__device__ float g_h[NN * HID];
__device__ float g_xl[NN * HID];
__device__ float g_xr[NN * HID];
__device__ float g_out[NN * HID];
__device__ float g_elog[(size_t)TOTE * NH];
__device__ float g_max[NN * NH];
__device__ float g_den[NN * NH];
__device__ float g_meansum[EDD];
__device__ float g_epself[HID];
__device__ float g_g1[NN * (HID / 2)];
__device__ float g_gate[NN];
__device__ float g_gmax[BB];
__device__ float g_gden[BB];
__device__ float g_pooled[BB * HID];
__device__ float g_r1[BB * 256];
__device__ float g_r2[BB * 128];
__device__ float g_r3[BB * 64];
__device__ __half g_wth[600000];   // transposed fp16 weights [N x Kpad] K-major

#define ID_H      0
#define ID_XL     1
#define ID_XR     2
#define ID_G1     3
#define ID_POOLED 4
#define ID_R1     5
#define ID_R2     6
#define ID_R3     7

// g_wth offsets (halves)
#define WTH_WIN    0
#define WTH_WLR(i) (24576 + (i) * 131072)      // [Wl rows 0-255 | Wr rows 256-511] x 256
#define WTH_WG1    (24576 + 4 * 131072)

__device__ __forceinline__ float* bufsel(int id) {
    switch (id) {
        case ID_H:      return g_h;
        case ID_XL:     return g_xl;
        case ID_XR:     return g_xr;
        case ID_G1:     return g_g1;
        case ID_POOLED: return g_pooled;
        case ID_R1:     return g_r1;
        case ID_R2:     return g_r2;
        case ID_R3:     return g_r3;
    }
    return nullptr;
}

__device__ __forceinline__ void atomicMaxF(float* addr, float val) {
    int* ai = (int*)addr;
    int old = *ai;
    while (__int_as_float(old) < val) {
        int assumed = old;
        old = atomicCAS(ai, assumed, __float_as_int(val));
        if (old == assumed) break;
    }
}

__device__ __forceinline__ void mma16(float* c, const uint32_t* a, const uint32_t* b) {
    asm volatile(
        "mma.sync.aligned.m16n8k16.row.col.f32.f16.f16.f32 "
        "{%0,%1,%2,%3}, {%4,%5,%6,%7}, {%8,%9}, {%0,%1,%2,%3};"
        : "+f"(c[0]), "+f"(c[1]), "+f"(c[2]), "+f"(c[3])
        : "r"(a[0]), "r"(a[1]), "r"(a[2]), "r"(a[3]), "r"(b[0]), "r"(b[1]));
}

__device__ __forceinline__ void ldsm4(uint32_t* r, uint32_t addr) {
    asm volatile("ldmatrix.sync.aligned.m8n8.x4.shared.b16 {%0,%1,%2,%3}, [%4];"
                 : "=r"(r[0]), "=r"(r[1]), "=r"(r[2]), "=r"(r[3]) : "r"(addr));
}

// ---------------- weight transpose to fp16: dst[n*Kpad+k] = h(W[k*N+n]) ----------------
__global__ void k_transposeh(const float* __restrict__ W, int K, int N, int Kpad, int dstoff) {
    int idx = blockIdx.x * blockDim.x + threadIdx.x;
    if (idx >= N * Kpad) return;
    int n = idx / Kpad, k = idx % Kpad;
    float v = (k < K) ? W[(size_t)k * N + n] : 0.f;
    g_wth[dstoff + idx] = __float2half_rn(v);
}

// ---------------- fp16 mma.sync GEMM ----------------
// block 128m x 128n, BK=32 halves, 256 threads (8 warps, warp tile 32m x 64n)
// C[gc<split]=c_id (stride ncout), else c_id2 at col gc-split (stride ncout)
#define HSTRIDE 40                        // halves per smem row (pad 32->40)
#define HA_B    (128 * HSTRIDE * 2)       // 10240 bytes per A buffer
#define HTILE_B (2 * HA_B)                // A + B per buffer = 20480
__global__ void __launch_bounds__(256) k_hgemm(
        const float* __restrict__ Aext, int a_id, int bt_off,
        const float* __restrict__ bias, int c_id, int c_id2,
        int M, int lda, int KS, int ldb, int ncout, int split,
        float scale, int act) {
    extern __shared__ char smc[];
    const float* A = (a_id < 0) ? Aext : bufsel(a_id);
    const __half* Wt = g_wth + bt_off;
    float* C  = bufsel(c_id);
    float* C2 = bufsel(c_id2);

    int tid = threadIdx.x, lane = tid & 31, wid = tid >> 5;
    int wm = wid & 3, wn = wid >> 2;       // 32 rows, 64 cols per warp
    int m0 = blockIdx.y * 128;
    int n0g = blockIdx.x * 128;

    int arow = tid >> 1, ahalf = tid & 1;  // A staging: row, 16-half chunk
    const bool vec = ((lda & 3) == 0);

    uint32_t sbase;
    asm("{ .reg .u64 t; cvta.to.shared.u64 t, %1; cvt.u32.u64 %0, t; }" : "=r"(sbase) : "l"(smc));

    float pre[16];
    auto loadA_regs = [&](int kc) {
        int gm = m0 + arow;
        int k0 = kc * 32 + ahalf * 16;
        if (gm < M) {
            if (vec) {
#pragma unroll
                for (int i = 0; i < 4; i++) {
                    float4 t = *reinterpret_cast<const float4*>(A + (size_t)gm * lda + k0 + i * 4);
                    pre[i * 4 + 0] = t.x; pre[i * 4 + 1] = t.y;
                    pre[i * 4 + 2] = t.z; pre[i * 4 + 3] = t.w;
                }
            } else {
#pragma unroll
                for (int i = 0; i < 16; i++)
                    pre[i] = (k0 + i < lda) ? A[(size_t)gm * lda + k0 + i] : 0.f;
            }
        } else {
#pragma unroll
            for (int i = 0; i < 16; i++) pre[i] = 0.f;
        }
    };
    auto stsA = [&](int buf) {
        __half2* dst = (__half2*)(smc + buf * HTILE_B + (arow * HSTRIDE + ahalf * 16) * 2);
        uint32_t v[8];
#pragma unroll
        for (int i = 0; i < 8; i++) {
            __half2 p = __floats2half2_rn(pre[i * 2], pre[i * 2 + 1]);
            v[i] = *reinterpret_cast<uint32_t*>(&p);
        }
        *reinterpret_cast<uint4*>(dst)     = *reinterpret_cast<uint4*>(v);
        *reinterpret_cast<uint4*>(dst + 4) = *reinterpret_cast<uint4*>(v + 4);
    };
    auto loadB = [&](int kc, int buf) {
        uint32_t bb = sbase + buf * HTILE_B + HA_B;
#pragma unroll
        for (int j = 0; j < 2; j++) {
            int flat = tid + j * 256;      // 512 chunks of 16B (8 halves)
            int n = flat >> 2, c8 = flat & 3;
            uint32_t dst = bb + (n * HSTRIDE + c8 * 8) * 2;
            const __half* src = Wt + (size_t)(n0g + n) * ldb + kc * 32 + c8 * 8;
            asm volatile("cp.async.cg.shared.global [%0], [%1], 16;" :: "r"(dst), "l"(src) : "memory");
        }
    };

    float acc[2][8][4];
#pragma unroll
    for (int mi = 0; mi < 2; mi++)
#pragma unroll
        for (int ni = 0; ni < 8; ni++)
#pragma unroll
            for (int e = 0; e < 4; e++) acc[mi][ni][e] = 0.f;

    loadA_regs(0);
    loadB(0, 0);
    stsA(0);
    asm volatile("cp.async.commit_group;\n\tcp.async.wait_group 0;" ::: "memory");
    __syncthreads();

    int lr8 = (lane & 7) + ((lane >> 3) & 1) * 8;   // ldmatrix row within 16
    int lk8 = (lane >> 4) * 8;                      // ldmatrix k-col offset

    for (int kc = 0; kc < KS; kc++) {
        int cur = kc & 1, nxt = 1 - cur;
        if (kc + 1 < KS) {
            loadA_regs(kc + 1);
            loadB(kc + 1, nxt);
            asm volatile("cp.async.commit_group;" ::: "memory");
        }
        uint32_t abase = sbase + cur * HTILE_B;
        uint32_t bbase = abase + HA_B;
#pragma unroll
        for (int h = 0; h < 2; h++) {           // two k16 steps per BK=32
            uint32_t af[2][4];
#pragma unroll
            for (int mi = 0; mi < 2; mi++) {
                uint32_t addr = abase + (((wm * 32 + mi * 16) + lr8) * HSTRIDE + h * 16 + lk8) * 2;
                ldsm4(af[mi], addr);
            }
            uint32_t bf[8][2];
#pragma unroll
            for (int nb = 0; nb < 4; nb++) {    // 16 n-rows per ldsm4
                uint32_t q[4];
                uint32_t addr = bbase + (((wn * 64 + nb * 16) + lr8) * HSTRIDE + h * 16 + lk8) * 2;
                ldsm4(q, addr);
                bf[nb * 2 + 0][0] = q[0]; bf[nb * 2 + 0][1] = q[2];
                bf[nb * 2 + 1][0] = q[1]; bf[nb * 2 + 1][1] = q[3];
            }
#pragma unroll
            for (int mi = 0; mi < 2; mi++)
#pragma unroll
                for (int ni = 0; ni < 8; ni++)
                    mma16(acc[mi][ni], af[mi], bf[ni]);
        }
        if (kc + 1 < KS) {
            stsA(nxt);
            asm volatile("cp.async.wait_group 0;" ::: "memory");
            __syncthreads();
        }
    }

    // epilogue
    int lq = lane >> 2, lr = lane & 3;
#pragma unroll
    for (int mi = 0; mi < 2; mi++) {
#pragma unroll
        for (int half = 0; half < 2; half++) {
            int gr = m0 + wm * 32 + mi * 16 + lq + half * 8;
            if (gr >= M) continue;
#pragma unroll
            for (int ni = 0; ni < 8; ni++) {
                int gc = n0g + wn * 64 + ni * 8 + 2 * lr;
                float v0 = acc[mi][ni][half * 2 + 0];
                float v1 = acc[mi][ni][half * 2 + 1];
                if (bias) { v0 += __ldg(&bias[gc]); v1 += __ldg(&bias[gc + 1]); }
                v0 *= scale; v1 *= scale;
                if (act == 1) { v0 = v0 > 0.f ? v0 : 0.f; v1 = v1 > 0.f ? v1 : 0.f; }
                else if (act == 2) {
                    v0 = v0 > 0.f ? v0 : expm1f(v0);
                    v1 = v1 > 0.f ? v1 : expm1f(v1);
                }
                float* Cp = C; int gcol = gc;
                if (gc >= split) { Cp = C2; gcol = gc - split; }
                *reinterpret_cast<float2*>(Cp + (size_t)gr * ncout + gcol) = make_float2(v0, v1);
            }
        }
    }
}

// ---------------- small init kernels ----------------
__global__ void k_zero_small() {
    int i = threadIdx.x;
    if (i < EDD) g_meansum[i] = 0.f;
}

__global__ void k_init_out() {
    int i = blockIdx.x * blockDim.x + threadIdx.x;
    if (i < NN * HID) g_out[i] = 0.f;
}

__global__ void k_init_md() {
    int i = blockIdx.x * blockDim.x + threadIdx.x;
    if (i < NN * NH) { g_max[i] = -1e30f; g_den[i] = 0.f; }
}

__global__ void k_init_pool() {
    int i = blockIdx.x * blockDim.x + threadIdx.x;
    if (i < BB) { g_gmax[i] = -1e30f; g_gden[i] = 0.f; }
    if (i < BB * HID) g_pooled[i] = 0.f;
}

// ---------------- column mean of edge_attr ----------------
__global__ void k_mean(const float* __restrict__ ea) {
    float loc[EDD];
#pragma unroll
    for (int k = 0; k < EDD; k++) loc[k] = 0.f;
    for (int e = blockIdx.x * blockDim.x + threadIdx.x; e < EE; e += gridDim.x * blockDim.x) {
#pragma unroll
        for (int k = 0; k < EDD; k++) loc[k] += ea[(size_t)e * EDD + k];
    }
#pragma unroll
    for (int k = 0; k < EDD; k++) {
        float v = loc[k];
#pragma unroll
        for (int o = 16; o; o >>= 1) v += __shfl_xor_sync(0xffffffffu, v, o);
        if ((threadIdx.x & 31) == 0) atomicAdd(&g_meansum[k], v);
    }
}

__global__ void k_epself(const float* __restrict__ We) {
    int j = threadIdx.x;
    const float invE = 1.f / (float)EE;
    float s = 0.f;
#pragma unroll
    for (int k = 0; k < EDD; k++) s += g_meansum[k] * invE * We[k * HID + j];
    g_epself[j] = s;
}

// ---------------- SIMT GEMM (small readout mats only) ----------------
__global__ void k_gemm(const float* __restrict__ Aext, int a_id,
                       const float* __restrict__ B, const float* __restrict__ bias,
                       int c_id, int M, int K, int Nc, float scale, int act) {
    __shared__ float As[16][65];
    __shared__ float Bs[16][65];
    const float* A = (a_id < 0) ? Aext : bufsel(a_id);
    float* Cp = bufsel(c_id);

    int t = threadIdx.x;
    int tx = t & 15, ty = t >> 4;
    int n0 = blockIdx.x * 64, m0 = blockIdx.y * 64;
    float acc[4][4] = {};

    for (int kk = 0; kk < K; kk += 16) {
#pragma unroll
        for (int j = 0; j < 4; j++) {
            int idx = t + j * 256;
            int m = idx >> 4, k = idx & 15;
            int gm = m0 + m, gk = kk + k;
            As[k][m] = (gm < M && gk < K) ? A[(size_t)gm * K + gk] : 0.f;
        }
#pragma unroll
        for (int j = 0; j < 4; j++) {
            int idx = t + j * 256;
            int k = idx >> 6, n = idx & 63;
            int gk = kk + k;
            Bs[k][n] = (gk < K) ? B[(size_t)gk * Nc + n0 + n] : 0.f;
        }
        __syncthreads();
#pragma unroll
        for (int k = 0; k < 16; k++) {
            float a[4], b[4];
#pragma unroll
            for (int i = 0; i < 4; i++) a[i] = As[k][ty + 16 * i];
#pragma unroll
            for (int j = 0; j < 4; j++) b[j] = Bs[k][tx + 16 * j];
#pragma unroll
            for (int i = 0; i < 4; i++)
#pragma unroll
                for (int j = 0; j < 4; j++) acc[i][j] += a[i] * b[j];
        }
        __syncthreads();
    }
#pragma unroll
    for (int i = 0; i < 4; i++) {
        int gm = m0 + ty + 16 * i;
        if (gm >= M) continue;
#pragma unroll
        for (int j = 0; j < 4; j++) {
            int gn = n0 + tx + 16 * j;
            float v = acc[i][j];
            if (bias) v += bias[gn];
            v *= scale;
            if (act == 1) v = v > 0.f ? v : 0.f;
            else if (act == 2) v = v > 0.f ? v : expm1f(v);
            Cp[(size_t)gm * Nc + gn] = v;
        }
    }
}

// ---------------- GATv2 edge logits + segment max ----------------
__global__ void k_logits(const int* __restrict__ ei, const float* __restrict__ ea,
                         const float* __restrict__ We, const float* __restrict__ att) {
    __shared__ float sWe[EDD * HID];
    __shared__ float satt[HID];
    __shared__ float sep[HID];
    for (int i = threadIdx.x; i < EDD * HID; i += blockDim.x) sWe[i] = We[i];
    for (int i = threadIdx.x; i < HID; i += blockDim.x) { satt[i] = att[i]; sep[i] = g_epself[i]; }
    __syncthreads();

    int lane = threadIdx.x & 31;
    int warp = (blockIdx.x * blockDim.x + threadIdx.x) >> 5;
    int nwarps = (gridDim.x * blockDim.x) >> 5;

    for (int e = warp; e < TOTE; e += nwarps) {
        int src, tgt;
        float eav = 0.f;
        bool slf = (e >= EE);
        if (slf) { src = e - EE; tgt = src; }
        else {
            src = ei[e]; tgt = ei[EE + e];
            if (lane < EDD) eav = ea[(size_t)e * EDD + lane];
        }
        const float* xlr = g_xl + (size_t)src * HID;
        const float* xrr = g_xr + (size_t)tgt * HID;
#pragma unroll
        for (int hh = 0; hh < NH; hh++) {
            int cc = hh * CC + lane;
            float ep;
            if (slf) ep = sep[cc];
            else {
                ep = 0.f;
#pragma unroll
                for (int k = 0; k < EDD; k++)
                    ep += __shfl_sync(0xffffffffu, eav, k) * sWe[k * HID + cc];
            }
            float s = xlr[cc] + xrr[cc] + ep;
            s = s > 0.f ? s : NEG_SLOPE * s;
            float v = s * satt[cc];
#pragma unroll
            for (int o = 16; o; o >>= 1) v += __shfl_xor_sync(0xffffffffu, v, o);
            if (lane == hh) {
                g_elog[(size_t)e * NH + hh] = v;
                atomicMaxF(&g_max[tgt * NH + hh], v);
            }
        }
    }
}

__global__ void k_expnorm(const int* __restrict__ ei) {
    int idx = blockIdx.x * blockDim.x + threadIdx.x;
    if (idx >= TOTE * NH) return;
    int e = idx >> 3, hh = idx & 7;
    int tgt = (e < EE) ? ei[EE + e] : (e - EE);
    float v = __expf(g_elog[idx] - g_max[tgt * NH + hh]);
    g_elog[idx] = v;
    atomicAdd(&g_den[tgt * NH + hh], v);
}

__global__ void k_agg(const int* __restrict__ ei) {
    int lane = threadIdx.x & 31;
    int warp = (blockIdx.x * blockDim.x + threadIdx.x) >> 5;
    int nwarps = (gridDim.x * blockDim.x) >> 5;
    for (int e = warp; e < TOTE; e += nwarps) {
        int src, tgt;
        if (e >= EE) { src = e - EE; tgt = src; }
        else { src = ei[e]; tgt = ei[EE + e]; }
        float num = 0.f, den = 0.f;
        if (lane < NH) {
            num = g_elog[(size_t)e * NH + lane];
            den = g_den[tgt * NH + lane];
        }
        const float* xlr = g_xl + (size_t)src * HID;
        float* orow = g_out + (size_t)tgt * HID;
#pragma unroll
        for (int hh = 0; hh < NH; hh++) {
            float a = __shfl_sync(0xffffffffu, num, hh) /
                      (__shfl_sync(0xffffffffu, den, hh) + 1e-16f);
            atomicAdd(&orow[hh * CC + lane], a * xlr[hh * CC + lane]);
        }
    }
}

// h = elu((out + b_gat) * BN_S) + h; also re-zero g_out for the next layer
__global__ void k_update(const float* __restrict__ bgat) {
    int idx = blockIdx.x * blockDim.x + threadIdx.x;
    if (idx >= NN * HID) return;
    int col = idx & (HID - 1);
    float v = (g_out[idx] + bgat[col]) * BN_SCALE;
    v = v > 0.f ? v : expm1f(v);
    g_h[idx] = v + g_h[idx];
    g_out[idx] = 0.f;
}

__global__ void k_gatedot(const float* __restrict__ Wg2, const float* __restrict__ bg2) {
    int lane = threadIdx.x & 31;
    int warp = (blockIdx.x * blockDim.x + threadIdx.x) >> 5;
    if (warp >= NN) return;
    float s = 0.f;
#pragma unroll
    for (int j = lane; j < 128; j += 32) s += g_g1[(size_t)warp * 128 + j] * Wg2[j];
#pragma unroll
    for (int o = 16; o; o >>= 1) s += __shfl_xor_sync(0xffffffffu, s, o);
    if (lane == 0) g_gate[warp] = s + bg2[0];
}

__global__ void k_gpool_max(const int* __restrict__ batch) {
    int n = blockIdx.x * blockDim.x + threadIdx.x;
    if (n < NN) atomicMaxF(&g_gmax[batch[n]], g_gate[n]);
}

__global__ void k_gpool_exp(const int* __restrict__ batch) {
    int n = blockIdx.x * blockDim.x + threadIdx.x;
    if (n >= NN) return;
    int b = batch[n];
    float v = __expf(g_gate[n] - g_gmax[b]);
    g_gate[n] = v;
    atomicAdd(&g_gden[b], v);
}

__global__ void k_pool(const int* __restrict__ batch) {
    int lane = threadIdx.x & 31;
    int warp = (blockIdx.x * blockDim.x + threadIdx.x) >> 5;
    if (warp >= NN) return;
    int b = batch[warp];
    float a = g_gate[warp] / (g_gden[b] + 1e-16f);
    const float* hr = g_h + (size_t)warp * HID;
    float* pr = g_pooled + (size_t)b * HID;
#pragma unroll
    for (int j = lane; j < HID; j += 32) atomicAdd(&pr[j], a * hr[j]);
}

__global__ void k_final(const float* __restrict__ W4, const float* __restrict__ b4,
                        float* __restrict__ out) {
    int b = blockIdx.x * blockDim.x + threadIdx.x;
    if (b >= BB) return;
    float s = b4[0];
#pragma unroll
    for (int k = 0; k < 64; k++) s += g_r3[b * 64 + k] * W4[k];
    out[b] = s;
}

// ---------------- host orchestration ----------------
extern "C" void kernel_launch(void* const* d_in, const int* in_sizes, int n_in,
                              void* d_out, int out_size) {
    const float* x     = (const float*)d_in[0];
    const int*   ei    = (const int*)  d_in[1];
    const float* ea    = (const float*)d_in[2];
    const int*   batch = (const int*)  d_in[3];
    const float* W_in  = (const float*)d_in[4];
    const float* b_in  = (const float*)d_in[5];
    const float* Wl    = (const float*)d_in[6];
    const float* Wr    = (const float*)d_in[7];
    const float* We    = (const float*)d_in[8];
    const float* att   = (const float*)d_in[9];
    const float* b_gat = (const float*)d_in[10];
    const float* Wg1   = (const float*)d_in[11];
    const float* bg1   = (const float*)d_in[12];
    const float* Wg2   = (const float*)d_in[13];
    const float* bg2   = (const float*)d_in[14];
    const float* W1    = (const float*)d_in[15];
    const float* b1    = (const float*)d_in[16];
    const float* W2    = (const float*)d_in[17];
    const float* b2    = (const float*)d_in[18];
    const float* W3    = (const float*)d_in[19];
    const float* b3    = (const float*)d_in[20];
    const float* W4    = (const float*)d_in[21];
    const float* b4    = (const float*)d_in[22];
    float* out = (float*)d_out;

    const int SMEMH = 2 * HTILE_B;  // 40960
    cudaFuncSetAttribute(k_hgemm, cudaFuncAttributeMaxDynamicSharedMemorySize, SMEMH);

    const int MTB = (NN + 127) / 128;  // 782
    dim3 thr(256);

    // fp16 transposed weights: W_in [256x96], per-layer [Wl|Wr] as [512x256], Wg1 [128x256]
    k_transposeh<<<(256 * 96 + 255) / 256, 256>>>(W_in, IND, HID, 96, WTH_WIN);
    for (int i = 0; i < NL; i++) {
        k_transposeh<<<(256 * 256 + 255) / 256, 256>>>(Wl + (size_t)i * 65536, HID, HID, 256, WTH_WLR(i));
        k_transposeh<<<(256 * 256 + 255) / 256, 256>>>(Wr + (size_t)i * 65536, HID, HID, 256, WTH_WLR(i) + 65536);
    }
    k_transposeh<<<(128 * 256 + 255) / 256, 256>>>(Wg1, HID, 128, 256, WTH_WG1);

    // edge_attr column mean + upfront zeroing of the aggregation buffer
    k_zero_small<<<1, 32>>>();
    k_mean<<<256, 256>>>(ea);
    k_init_out<<<(NN * HID + 255) / 256, thr>>>();

    // input projection: h = elu((x @ W_in + b_in) * BN_S)
    k_hgemm<<<dim3(2, MTB), thr, SMEMH>>>(x, -1, WTH_WIN, b_in, ID_H, ID_H,
                                          NN, IND, 3, 96, 256, 256, BN_SCALE, 2);

    for (int i = 0; i < NL; i++) {
        const float* Wei = We + (size_t)i * EDD * HID;
        const float* ati = att + (size_t)i * NH * CC;
        const float* bgi = b_gat + (size_t)i * HID;

        // fused xl|xr GEMM: N=512, cols<256 -> g_xl, cols>=256 -> g_xr
        k_hgemm<<<dim3(4, MTB), thr, SMEMH>>>(nullptr, ID_H, WTH_WLR(i), nullptr, ID_XL, ID_XR,
                                              NN, HID, 8, 256, 256, 256, 1.f, 0);
        k_epself<<<1, HID>>>(Wei);
        k_init_md<<<(NN * NH + 255) / 256, thr>>>();
        k_logits<<<8192, thr>>>(ei, ea, Wei, ati);
        k_expnorm<<<(TOTE * NH + 255) / 256, thr>>>(ei);
        k_agg<<<8192, thr>>>(ei);
        k_update<<<(NN * HID + 255) / 256, thr>>>(bgi);
    }

    // global attention pooling
    k_hgemm<<<dim3(1, MTB), thr, SMEMH>>>(nullptr, ID_H, WTH_WG1, bg1, ID_G1, ID_G1,
                                          NN, HID, 8, 256, 128, 128, 1.f, 1);
    k_gatedot<<<(NN * 32 + 255) / 256, thr>>>(Wg2, bg2);
    k_init_pool<<<(BB * HID + 255) / 256, thr>>>();
    k_gpool_max<<<(NN + 255) / 256, thr>>>(batch);
    k_gpool_exp<<<(NN + 255) / 256, thr>>>(batch);
    k_pool<<<(NN * 32 + 255) / 256, thr>>>(batch);

    // readout MLP (small; SIMT)
    k_gemm<<<dim3(256 / 64, BB / 64), thr>>>(nullptr, ID_POOLED, W1, b1, ID_R1, BB, HID, 256, BN_SCALE, 1);
    k_gemm<<<dim3(128 / 64, BB / 64), thr>>>(nullptr, ID_R1, W2, b2, ID_R2, BB, 256, 128, BN_SCALE, 1);
    k_gemm<<<dim3(64 / 64, BB / 64), thr>>>(nullptr, ID_R2, W3, b3, ID_R3, BB, 128, 64, 1.f, 1);
    k_final<<<(BB + 255) / 256, thr>>>(W4, b4, out);
}

// round 6
// speedup vs baseline: 2.4036x; 1.2478x over previous
#include <cuda_runtime.h>
#include <cuda_fp16.h>
#include <math.h>
#include <stdint.h>

#define NN   100000
#define EE   220000
#define BB   4096
#define IND  75
#define HID  256
#define NH   8
#define CC   32
#define EDD  10
#define NL   4
#define TOTE (EE + NN)
#define BN_SCALE 0.9999950000375f
#define NEG_SLOPE 0.2f

// ---------------- scratch (device globals; no allocation allowed) ----------------
__device__ float g_h[NN * HID];
__device__ float g_xl[NN * HID];
__device__ float g_xr[NN * HID];
__device__ float g_elog[(size_t)TOTE * NH];
__device__ float g_meansum[EDD];
__device__ float g_epself[HID];
__device__ float g_g1[NN * (HID / 2)];
__device__ float g_gate[NN];
__device__ float g_pooled[BB * HID];
__device__ float g_r1[BB * 256];
__device__ float g_r2[BB * 128];
__device__ float g_r3[BB * 64];
__device__ __half g_wth[600000];   // transposed fp16 weights [N x Kpad] K-major
// CSR over targets
__device__ int g_rowptr[NN + 1];
__device__ int g_cursor[NN];
__device__ int g_eidx[TOTE];
__device__ int g_bsum[1024];

#define ID_H      0
#define ID_XL     1
#define ID_XR     2
#define ID_G1     3
#define ID_POOLED 4
#define ID_R1     5
#define ID_R2     6
#define ID_R3     7

// g_wth offsets (halves)
#define WTH_WIN    0
#define WTH_WLR(i) (24576 + (i) * 131072)
#define WTH_WG1    (24576 + 4 * 131072)

__device__ __forceinline__ float* bufsel(int id) {
    switch (id) {
        case ID_H:      return g_h;
        case ID_XL:     return g_xl;
        case ID_XR:     return g_xr;
        case ID_G1:     return g_g1;
        case ID_POOLED: return g_pooled;
        case ID_R1:     return g_r1;
        case ID_R2:     return g_r2;
        case ID_R3:     return g_r3;
    }
    return nullptr;
}

__device__ __forceinline__ void mma16(float* c, const uint32_t* a, const uint32_t* b) {
    asm volatile(
        "mma.sync.aligned.m16n8k16.row.col.f32.f16.f16.f32 "
        "{%0,%1,%2,%3}, {%4,%5,%6,%7}, {%8,%9}, {%0,%1,%2,%3};"
        : "+f"(c[0]), "+f"(c[1]), "+f"(c[2]), "+f"(c[3])
        : "r"(a[0]), "r"(a[1]), "r"(a[2]), "r"(a[3]), "r"(b[0]), "r"(b[1]));
}

__device__ __forceinline__ void ldsm4(uint32_t* r, uint32_t addr) {
    asm volatile("ldmatrix.sync.aligned.m8n8.x4.shared.b16 {%0,%1,%2,%3}, [%4];"
                 : "=r"(r[0]), "=r"(r[1]), "=r"(r[2]), "=r"(r[3]) : "r"(addr));
}

// ---------------- weight transpose to fp16 ----------------
__global__ void k_transposeh(const float* __restrict__ W, int K, int N, int Kpad, int dstoff) {
    int idx = blockIdx.x * blockDim.x + threadIdx.x;
    if (idx >= N * Kpad) return;
    int n = idx / Kpad, k = idx % Kpad;
    float v = (k < K) ? W[(size_t)k * N + n] : 0.f;
    g_wth[dstoff + idx] = __float2half_rn(v);
}

// ---------------- fp16 mma.sync GEMM (unchanged from R5) ----------------
#define HSTRIDE 40
#define HA_B    (128 * HSTRIDE * 2)
#define HTILE_B (2 * HA_B)
__global__ void __launch_bounds__(256) k_hgemm(
        const float* __restrict__ Aext, int a_id, int bt_off,
        const float* __restrict__ bias, int c_id, int c_id2,
        int M, int lda, int KS, int ldb, int ncout, int split,
        float scale, int act) {
    extern __shared__ char smc[];
    const float* A = (a_id < 0) ? Aext : bufsel(a_id);
    const __half* Wt = g_wth + bt_off;
    float* C  = bufsel(c_id);
    float* C2 = bufsel(c_id2);

    int tid = threadIdx.x, lane = tid & 31, wid = tid >> 5;
    int wm = wid & 3, wn = wid >> 2;
    int m0 = blockIdx.y * 128;
    int n0g = blockIdx.x * 128;

    int arow = tid >> 1, ahalf = tid & 1;
    const bool vec = ((lda & 3) == 0);

    uint32_t sbase;
    asm("{ .reg .u64 t; cvta.to.shared.u64 t, %1; cvt.u32.u64 %0, t; }" : "=r"(sbase) : "l"(smc));

    float pre[16];
    auto loadA_regs = [&](int kc) {
        int gm = m0 + arow;
        int k0 = kc * 32 + ahalf * 16;
        if (gm < M) {
            if (vec) {
#pragma unroll
                for (int i = 0; i < 4; i++) {
                    float4 t = *reinterpret_cast<const float4*>(A + (size_t)gm * lda + k0 + i * 4);
                    pre[i * 4 + 0] = t.x; pre[i * 4 + 1] = t.y;
                    pre[i * 4 + 2] = t.z; pre[i * 4 + 3] = t.w;
                }
            } else {
#pragma unroll
                for (int i = 0; i < 16; i++)
                    pre[i] = (k0 + i < lda) ? A[(size_t)gm * lda + k0 + i] : 0.f;
            }
        } else {
#pragma unroll
            for (int i = 0; i < 16; i++) pre[i] = 0.f;
        }
    };
    auto stsA = [&](int buf) {
        __half2* dst = (__half2*)(smc + buf * HTILE_B + (arow * HSTRIDE + ahalf * 16) * 2);
        uint32_t v[8];
#pragma unroll
        for (int i = 0; i < 8; i++) {
            __half2 p = __floats2half2_rn(pre[i * 2], pre[i * 2 + 1]);
            v[i] = *reinterpret_cast<uint32_t*>(&p);
        }
        *reinterpret_cast<uint4*>(dst)     = *reinterpret_cast<uint4*>(v);
        *reinterpret_cast<uint4*>(dst + 4) = *reinterpret_cast<uint4*>(v + 4);
    };
    auto loadB = [&](int kc, int buf) {
        uint32_t bb = sbase + buf * HTILE_B + HA_B;
#pragma unroll
        for (int j = 0; j < 2; j++) {
            int flat = tid + j * 256;
            int n = flat >> 2, c8 = flat & 3;
            uint32_t dst = bb + (n * HSTRIDE + c8 * 8) * 2;
            const __half* src = Wt + (size_t)(n0g + n) * ldb + kc * 32 + c8 * 8;
            asm volatile("cp.async.cg.shared.global [%0], [%1], 16;" :: "r"(dst), "l"(src) : "memory");
        }
    };

    float acc[2][8][4];
#pragma unroll
    for (int mi = 0; mi < 2; mi++)
#pragma unroll
        for (int ni = 0; ni < 8; ni++)
#pragma unroll
            for (int e = 0; e < 4; e++) acc[mi][ni][e] = 0.f;

    loadA_regs(0);
    loadB(0, 0);
    stsA(0);
    asm volatile("cp.async.commit_group;\n\tcp.async.wait_group 0;" ::: "memory");
    __syncthreads();

    int lr8 = (lane & 7) + ((lane >> 3) & 1) * 8;
    int lk8 = (lane >> 4) * 8;

    for (int kc = 0; kc < KS; kc++) {
        int cur = kc & 1, nxt = 1 - cur;
        if (kc + 1 < KS) {
            loadA_regs(kc + 1);
            loadB(kc + 1, nxt);
            asm volatile("cp.async.commit_group;" ::: "memory");
        }
        uint32_t abase = sbase + cur * HTILE_B;
        uint32_t bbase = abase + HA_B;
#pragma unroll
        for (int h = 0; h < 2; h++) {
            uint32_t af[2][4];
#pragma unroll
            for (int mi = 0; mi < 2; mi++) {
                uint32_t addr = abase + (((wm * 32 + mi * 16) + lr8) * HSTRIDE + h * 16 + lk8) * 2;
                ldsm4(af[mi], addr);
            }
            uint32_t bf[8][2];
#pragma unroll
            for (int nb = 0; nb < 4; nb++) {
                uint32_t q[4];
                uint32_t addr = bbase + (((wn * 64 + nb * 16) + lr8) * HSTRIDE + h * 16 + lk8) * 2;
                ldsm4(q, addr);
                bf[nb * 2 + 0][0] = q[0]; bf[nb * 2 + 0][1] = q[2];
                bf[nb * 2 + 1][0] = q[1]; bf[nb * 2 + 1][1] = q[3];
            }
#pragma unroll
            for (int mi = 0; mi < 2; mi++)
#pragma unroll
                for (int ni = 0; ni < 8; ni++)
                    mma16(acc[mi][ni], af[mi], bf[ni]);
        }
        if (kc + 1 < KS) {
            stsA(nxt);
            asm volatile("cp.async.wait_group 0;" ::: "memory");
            __syncthreads();
        }
    }

    int lq = lane >> 2, lr = lane & 3;
#pragma unroll
    for (int mi = 0; mi < 2; mi++) {
#pragma unroll
        for (int half = 0; half < 2; half++) {
            int gr = m0 + wm * 32 + mi * 16 + lq + half * 8;
            if (gr >= M) continue;
#pragma unroll
            for (int ni = 0; ni < 8; ni++) {
                int gc = n0g + wn * 64 + ni * 8 + 2 * lr;
                float v0 = acc[mi][ni][half * 2 + 0];
                float v1 = acc[mi][ni][half * 2 + 1];
                if (bias) { v0 += __ldg(&bias[gc]); v1 += __ldg(&bias[gc + 1]); }
                v0 *= scale; v1 *= scale;
                if (act == 1) { v0 = v0 > 0.f ? v0 : 0.f; v1 = v1 > 0.f ? v1 : 0.f; }
                else if (act == 2) {
                    v0 = v0 > 0.f ? v0 : expm1f(v0);
                    v1 = v1 > 0.f ? v1 : expm1f(v1);
                }
                float* Cp = C; int gcol = gc;
                if (gc >= split) { Cp = C2; gcol = gc - split; }
                *reinterpret_cast<float2*>(Cp + (size_t)gr * ncout + gcol) = make_float2(v0, v1);
            }
        }
    }
}

// ---------------- CSR build ----------------
__global__ void k_deg_init() {
    int i = blockIdx.x * blockDim.x + threadIdx.x;
    if (i <= NN) g_rowptr[i] = (i == 0) ? 0 : 1;   // self loop baseline
}
__global__ void k_deg_count(const int* __restrict__ ei) {
    int e = blockIdx.x * blockDim.x + threadIdx.x;
    if (e < EE) atomicAdd(&g_rowptr[ei[EE + e] + 1], 1);
}
#define SCB 256
__global__ void k_scan1() {
    __shared__ int s[SCB];
    int i = blockIdx.x * SCB + threadIdx.x;
    int v = (i < NN) ? g_rowptr[1 + i] : 0;
    s[threadIdx.x] = v;
    __syncthreads();
#pragma unroll
    for (int off = 1; off < SCB; off <<= 1) {
        int t = 0;
        if ((int)threadIdx.x >= off) t = s[threadIdx.x - off];
        __syncthreads();
        if ((int)threadIdx.x >= off) s[threadIdx.x] += t;
        __syncthreads();
    }
    if (i < NN) g_rowptr[1 + i] = s[threadIdx.x];
    if (threadIdx.x == SCB - 1) g_bsum[blockIdx.x] = s[threadIdx.x];
}
__global__ void k_scan2(int nb) {
    __shared__ int s[512];
    int v = ((int)threadIdx.x < nb) ? g_bsum[threadIdx.x] : 0;
    s[threadIdx.x] = v;
    __syncthreads();
#pragma unroll
    for (int off = 1; off < 512; off <<= 1) {
        int t = 0;
        if ((int)threadIdx.x >= off) t = s[threadIdx.x - off];
        __syncthreads();
        if ((int)threadIdx.x >= off) s[threadIdx.x] += t;
        __syncthreads();
    }
    if ((int)threadIdx.x < nb) g_bsum[threadIdx.x] = s[threadIdx.x];
}
__global__ void k_scan3() {
    int i = blockIdx.x * SCB + threadIdx.x;
    if (blockIdx.x > 0 && i < NN) g_rowptr[1 + i] += g_bsum[blockIdx.x - 1];
    if (i < NN) g_cursor[i] = (i == 0) ? 0 : 0;  // placeholder; cursor set below
}
__global__ void k_cursor_init() {
    int i = blockIdx.x * blockDim.x + threadIdx.x;
    if (i < NN) g_cursor[i] = g_rowptr[i];
}
__global__ void k_scatter(const int* __restrict__ ei) {
    int idx = blockIdx.x * blockDim.x + threadIdx.x;
    if (idx >= TOTE) return;
    int tgt = (idx < EE) ? ei[EE + idx] : (idx - EE);
    int pos = atomicAdd(&g_cursor[tgt], 1);
    g_eidx[pos] = idx;
}

// ---------------- column mean of edge_attr ----------------
__global__ void k_zero_small() {
    int i = threadIdx.x;
    if (i < EDD) g_meansum[i] = 0.f;
}
__global__ void k_mean(const float* __restrict__ ea) {
    float loc[EDD];
#pragma unroll
    for (int k = 0; k < EDD; k++) loc[k] = 0.f;
    for (int e = blockIdx.x * blockDim.x + threadIdx.x; e < EE; e += gridDim.x * blockDim.x) {
#pragma unroll
        for (int k = 0; k < EDD; k++) loc[k] += ea[(size_t)e * EDD + k];
    }
#pragma unroll
    for (int k = 0; k < EDD; k++) {
        float v = loc[k];
#pragma unroll
        for (int o = 16; o; o >>= 1) v += __shfl_xor_sync(0xffffffffu, v, o);
        if ((threadIdx.x & 31) == 0) atomicAdd(&g_meansum[k], v);
    }
}
__global__ void k_epself(const float* __restrict__ We) {
    int j = threadIdx.x;
    const float invE = 1.f / (float)EE;
    float s = 0.f;
#pragma unroll
    for (int k = 0; k < EDD; k++) s += g_meansum[k] * invE * We[k * HID + j];
    g_epself[j] = s;
}

// ---------------- fused GAT layer: logits+softmax+aggregate+update ----------------
// warp per target node; CSR in-edges; no atomics
__global__ void __launch_bounds__(256) k_gat(const int* __restrict__ ei,
                                             const float* __restrict__ ea,
                                             const float* __restrict__ We,
                                             const float* __restrict__ att,
                                             const float* __restrict__ bgat) {
    __shared__ float sWe[EDD * HID];
    __shared__ float satt[HID];
    __shared__ float sep[HID];
    __shared__ float sbg[HID];
    for (int i = threadIdx.x; i < EDD * HID; i += blockDim.x) sWe[i] = We[i];
    for (int i = threadIdx.x; i < HID; i += blockDim.x) {
        satt[i] = att[i]; sep[i] = g_epself[i]; sbg[i] = bgat[i];
    }
    __syncthreads();

    int lane = threadIdx.x & 31;
    int gw = (blockIdx.x * blockDim.x + threadIdx.x) >> 5;
    int nwarps = (gridDim.x * blockDim.x) >> 5;

    for (int t = gw; t < NN; t += nwarps) {
        int r0 = g_rowptr[t], r1 = g_rowptr[t + 1];
        float xr[8];
#pragma unroll
        for (int j = 0; j < 8; j++) xr[j] = g_xr[(size_t)t * HID + j * 32 + lane];

        float mx[8];
#pragma unroll
        for (int j = 0; j < 8; j++) mx[j] = -1e30f;

        // pass 1: logits + per-head max
        for (int p = r0; p < r1; p++) {
            int e = g_eidx[p];
            bool slf = (e >= EE);
            int src;
            float eav = 0.f;
            if (slf) src = e - EE;
            else {
                src = ei[e];
                if (lane < EDD) eav = ea[(size_t)e * EDD + lane];
            }
            const float* xlr = g_xl + (size_t)src * HID;
            float lg[8];
#pragma unroll
            for (int j = 0; j < 8; j++) {
                int c = j * 32 + lane;
                float ep;
                if (slf) ep = sep[c];
                else {
                    ep = 0.f;
#pragma unroll
                    for (int k = 0; k < EDD; k++)
                        ep += __shfl_sync(0xffffffffu, eav, k) * sWe[k * HID + c];
                }
                float s = xlr[c] + xr[j] + ep;
                s = s > 0.f ? s : NEG_SLOPE * s;
                lg[j] = s * satt[c];
            }
#pragma unroll
            for (int o = 16; o; o >>= 1)
#pragma unroll
                for (int j = 0; j < 8; j++) lg[j] += __shfl_xor_sync(0xffffffffu, lg[j], o);
#pragma unroll
            for (int j = 0; j < 8; j++) mx[j] = fmaxf(mx[j], lg[j]);
            if (lane == 0) {
                float4 a = make_float4(lg[0], lg[1], lg[2], lg[3]);
                float4 b = make_float4(lg[4], lg[5], lg[6], lg[7]);
                float4* lp = (float4*)(g_elog + (size_t)p * NH);
                lp[0] = a; lp[1] = b;
            }
        }

        // pass 2: unnormalized weighted sum + denominator (softmax is linear)
        float den[8], acc[8];
#pragma unroll
        for (int j = 0; j < 8; j++) { den[j] = 0.f; acc[j] = 0.f; }
        for (int p = r0; p < r1; p++) {
            int e = g_eidx[p];
            int src = (e >= EE) ? (e - EE) : ei[e];
            const float4* lp = (const float4*)(g_elog + (size_t)p * NH);
            float4 a = lp[0], b = lp[1];
            float ex[8];
            ex[0] = __expf(a.x - mx[0]); ex[1] = __expf(a.y - mx[1]);
            ex[2] = __expf(a.z - mx[2]); ex[3] = __expf(a.w - mx[3]);
            ex[4] = __expf(b.x - mx[4]); ex[5] = __expf(b.y - mx[5]);
            ex[6] = __expf(b.z - mx[6]); ex[7] = __expf(b.w - mx[7]);
            const float* xlr = g_xl + (size_t)src * HID;
#pragma unroll
            for (int j = 0; j < 8; j++) {
                den[j] += ex[j];
                acc[j] += ex[j] * xlr[j * 32 + lane];
            }
        }
#pragma unroll
        for (int j = 0; j < 8; j++) {
            int c = j * 32 + lane;
            float v = (acc[j] / (den[j] + 1e-16f) + sbg[c]) * BN_SCALE;
            v = v > 0.f ? v : expm1f(v);
            size_t idx = (size_t)t * HID + c;
            g_h[idx] = v + g_h[idx];
        }
    }
}

// ---------------- SIMT GEMM (small readout mats) ----------------
__global__ void k_gemm(const float* __restrict__ Aext, int a_id,
                       const float* __restrict__ B, const float* __restrict__ bias,
                       int c_id, int M, int K, int Nc, float scale, int act) {
    __shared__ float As[16][65];
    __shared__ float Bs[16][65];
    const float* A = (a_id < 0) ? Aext : bufsel(a_id);
    float* Cp = bufsel(c_id);

    int t = threadIdx.x;
    int tx = t & 15, ty = t >> 4;
    int n0 = blockIdx.x * 64, m0 = blockIdx.y * 64;
    float acc[4][4] = {};

    for (int kk = 0; kk < K; kk += 16) {
#pragma unroll
        for (int j = 0; j < 4; j++) {
            int idx = t + j * 256;
            int m = idx >> 4, k = idx & 15;
            int gm = m0 + m, gk = kk + k;
            As[k][m] = (gm < M && gk < K) ? A[(size_t)gm * K + gk] : 0.f;
        }
#pragma unroll
        for (int j = 0; j < 4; j++) {
            int idx = t + j * 256;
            int k = idx >> 6, n = idx & 63;
            int gk = kk + k;
            Bs[k][n] = (gk < K) ? B[(size_t)gk * Nc + n0 + n] : 0.f;
        }
        __syncthreads();
#pragma unroll
        for (int k = 0; k < 16; k++) {
            float a[4], b[4];
#pragma unroll
            for (int i = 0; i < 4; i++) a[i] = As[k][ty + 16 * i];
#pragma unroll
            for (int j = 0; j < 4; j++) b[j] = Bs[k][tx + 16 * j];
#pragma unroll
            for (int i = 0; i < 4; i++)
#pragma unroll
                for (int j = 0; j < 4; j++) acc[i][j] += a[i] * b[j];
        }
        __syncthreads();
    }
#pragma unroll
    for (int i = 0; i < 4; i++) {
        int gm = m0 + ty + 16 * i;
        if (gm >= M) continue;
#pragma unroll
        for (int j = 0; j < 4; j++) {
            int gn = n0 + tx + 16 * j;
            float v = acc[i][j];
            if (bias) v += bias[gn];
            v *= scale;
            if (act == 1) v = v > 0.f ? v : 0.f;
            else if (act == 2) v = v > 0.f ? v : expm1f(v);
            Cp[(size_t)gm * Nc + gn] = v;
        }
    }
}

// ---------------- gate dot ----------------
__global__ void k_gatedot(const float* __restrict__ Wg2, const float* __restrict__ bg2) {
    int lane = threadIdx.x & 31;
    int warp = (blockIdx.x * blockDim.x + threadIdx.x) >> 5;
    if (warp >= NN) return;
    float s = 0.f;
#pragma unroll
    for (int j = lane; j < 128; j += 32) s += g_g1[(size_t)warp * 128 + j] * Wg2[j];
#pragma unroll
    for (int o = 16; o; o >>= 1) s += __shfl_xor_sync(0xffffffffu, s, o);
    if (lane == 0) g_gate[warp] = s + bg2[0];
}

// ---------------- fused pooling: warp per graph, binary search segments ----------------
__global__ void __launch_bounds__(256) k_poolf(const int* __restrict__ batch) {
    int lane = threadIdx.x & 31;
    int b = (blockIdx.x * blockDim.x + threadIdx.x) >> 5;
    if (b >= BB) return;

    int s0, s1;
    if (lane == 0) {
        int lo = 0, hi = NN;
        while (lo < hi) { int m = (lo + hi) >> 1; if (batch[m] < b) lo = m + 1; else hi = m; }
        s0 = lo;
        lo = s0; hi = NN;
        while (lo < hi) { int m = (lo + hi) >> 1; if (batch[m] < b + 1) lo = m + 1; else hi = m; }
        s1 = lo;
    }
    s0 = __shfl_sync(0xffffffffu, s0, 0);
    s1 = __shfl_sync(0xffffffffu, s1, 0);

    // per-graph gate max
    float mx = -1e30f;
    for (int n = s0 + lane; n < s1; n += 32) mx = fmaxf(mx, g_gate[n]);
#pragma unroll
    for (int o = 16; o; o >>= 1) mx = fmaxf(mx, __shfl_xor_sync(0xffffffffu, mx, o));

    float den = 0.f;
    float acc[8];
#pragma unroll
    for (int j = 0; j < 8; j++) acc[j] = 0.f;
    for (int n = s0; n < s1; n++) {
        float ex = __expf(g_gate[n] - mx);
        den += ex;
        const float* hr = g_h + (size_t)n * HID;
#pragma unroll
        for (int j = 0; j < 8; j++) acc[j] += ex * hr[j * 32 + lane];
    }
    float inv = 1.f / (den + 1e-16f);
#pragma unroll
    for (int j = 0; j < 8; j++)
        g_pooled[(size_t)b * HID + j * 32 + lane] = acc[j] * inv;
}

__global__ void k_final(const float* __restrict__ W4, const float* __restrict__ b4,
                        float* __restrict__ out) {
    int b = blockIdx.x * blockDim.x + threadIdx.x;
    if (b >= BB) return;
    float s = b4[0];
#pragma unroll
    for (int k = 0; k < 64; k++) s += g_r3[b * 64 + k] * W4[k];
    out[b] = s;
}

// ---------------- host orchestration ----------------
extern "C" void kernel_launch(void* const* d_in, const int* in_sizes, int n_in,
                              void* d_out, int out_size) {
    const float* x     = (const float*)d_in[0];
    const int*   ei    = (const int*)  d_in[1];
    const float* ea    = (const float*)d_in[2];
    const int*   batch = (const int*)  d_in[3];
    const float* W_in  = (const float*)d_in[4];
    const float* b_in  = (const float*)d_in[5];
    const float* Wl    = (const float*)d_in[6];
    const float* Wr    = (const float*)d_in[7];
    const float* We    = (const float*)d_in[8];
    const float* att   = (const float*)d_in[9];
    const float* b_gat = (const float*)d_in[10];
    const float* Wg1   = (const float*)d_in[11];
    const float* bg1   = (const float*)d_in[12];
    const float* Wg2   = (const float*)d_in[13];
    const float* bg2   = (const float*)d_in[14];
    const float* W1    = (const float*)d_in[15];
    const float* b1    = (const float*)d_in[16];
    const float* W2    = (const float*)d_in[17];
    const float* b2    = (const float*)d_in[18];
    const float* W3    = (const float*)d_in[19];
    const float* b3    = (const float*)d_in[20];
    const float* W4    = (const float*)d_in[21];
    const float* b4    = (const float*)d_in[22];
    float* out = (float*)d_out;

    const int SMEMH = 2 * HTILE_B;  // 40960
    cudaFuncSetAttribute(k_hgemm, cudaFuncAttributeMaxDynamicSharedMemorySize, SMEMH);

    const int MTB = (NN + 127) / 128;  // 782
    const int SCANB = (NN + SCB - 1) / SCB;  // 391
    dim3 thr(256);

    // fp16 transposed weights
    k_transposeh<<<(256 * 96 + 255) / 256, 256>>>(W_in, IND, HID, 96, WTH_WIN);
    for (int i = 0; i < NL; i++) {
        k_transposeh<<<(256 * 256 + 255) / 256, 256>>>(Wl + (size_t)i * 65536, HID, HID, 256, WTH_WLR(i));
        k_transposeh<<<(256 * 256 + 255) / 256, 256>>>(Wr + (size_t)i * 65536, HID, HID, 256, WTH_WLR(i) + 65536);
    }
    k_transposeh<<<(128 * 256 + 255) / 256, 256>>>(Wg1, HID, 128, 256, WTH_WG1);

    // CSR over targets (layer-invariant)
    k_deg_init<<<(NN + 256) / 256, thr>>>();
    k_deg_count<<<(EE + 255) / 256, thr>>>(ei);
    k_scan1<<<SCANB, SCB>>>();
    k_scan2<<<1, 512>>>(SCANB);
    k_scan3<<<SCANB, SCB>>>();
    k_cursor_init<<<(NN + 255) / 256, thr>>>();
    k_scatter<<<(TOTE + 255) / 256, thr>>>(ei);

    // edge_attr column mean
    k_zero_small<<<1, 32>>>();
    k_mean<<<256, 256>>>(ea);

    // input projection
    k_hgemm<<<dim3(2, MTB), thr, SMEMH>>>(x, -1, WTH_WIN, b_in, ID_H, ID_H,
                                          NN, IND, 3, 96, 256, 256, BN_SCALE, 2);

    for (int i = 0; i < NL; i++) {
        const float* Wei = We + (size_t)i * EDD * HID;
        const float* ati = att + (size_t)i * NH * CC;
        const float* bgi = b_gat + (size_t)i * HID;

        k_hgemm<<<dim3(4, MTB), thr, SMEMH>>>(nullptr, ID_H, WTH_WLR(i), nullptr, ID_XL, ID_XR,
                                              NN, HID, 8, 256, 256, 256, 1.f, 0);
        k_epself<<<1, HID>>>(Wei);
        k_gat<<<2048, thr>>>(ei, ea, Wei, ati, bgi);
    }

    // global attention pooling
    k_hgemm<<<dim3(1, MTB), thr, SMEMH>>>(nullptr, ID_H, WTH_WG1, bg1, ID_G1, ID_G1,
                                          NN, HID, 8, 256, 128, 128, 1.f, 1);
    k_gatedot<<<(NN * 32 + 255) / 256, thr>>>(Wg2, bg2);
    k_poolf<<<(BB * 32 + 255) / 256, thr>>>(batch);

    // readout MLP
    k_gemm<<<dim3(256 / 64, BB / 64), thr>>>(nullptr, ID_POOLED, W1, b1, ID_R1, BB, HID, 256, BN_SCALE, 1);
    k_gemm<<<dim3(128 / 64, BB / 64), thr>>>(nullptr, ID_R1, W2, b2, ID_R2, BB, 256, 128, BN_SCALE, 1);
    k_gemm<<<dim3(64 / 64, BB / 64), thr>>>(nullptr, ID_R2, W3, b3, ID_R3, BB, 128, 64, 1.f, 1);
    k_final<<<(BB + 255) / 256, thr>>>(W4, b4, out);
}

// round 7
// speedup vs baseline: 3.6462x; 1.5170x over previous
#include <cuda_runtime.h>
#include <cuda_fp16.h>
#include <math.h>
#include <stdint.h>

#define NN   100000
#define EE   220000
#define BB   4096
#define IND  75
#define HID  256
#define NH   8
#define CC   32
#define EDD  10
#define NL   4
#define TOTE (EE + NN)
#define BN_SCALE 0.9999950000375f
#define NEG_SLOPE 0.2f

// ---------------- scratch ----------------
__device__ float  g_h[NN * HID];
__device__ __half g_hh[NN * HID];     // fp16 mirror of h (GEMM A operand)
__device__ float  g_xr[NN * HID];
__device__ __half g_xlh[NN * HID];    // fp16 xl (edge gather source)
__device__ float  g_elog[(size_t)TOTE * NH];
__device__ float  g_meansum[EDD];
__device__ float  g_epself[HID];
__device__ float  g_g1[NN * (HID / 2)];
__device__ float  g_gate[NN];
__device__ float  g_pooled[BB * HID];
__device__ float  g_r1[BB * 256];
__device__ float  g_r2[BB * 128];
__device__ float  g_r3[BB * 64];
__device__ __half g_wth[600000];
__device__ int g_rowptr[NN + 1];
__device__ int g_cursor[NN];
__device__ int g_eidx[TOTE];
__device__ int g_bsum[1024];

#define ID_H      0
#define ID_XLH    1
#define ID_XR     2
#define ID_G1     3
#define ID_POOLED 4
#define ID_R1     5
#define ID_R2     6
#define ID_R3     7

#define WTH_WIN    0
#define WTH_WLR(i) (24576 + (i) * 131072)
#define WTH_WG1    (24576 + 4 * 131072)

__device__ __forceinline__ float* bufsel(int id) {
    switch (id) {
        case ID_H:      return g_h;
        case ID_XR:     return g_xr;
        case ID_G1:     return g_g1;
        case ID_POOLED: return g_pooled;
        case ID_R1:     return g_r1;
        case ID_R2:     return g_r2;
        case ID_R3:     return g_r3;
    }
    return nullptr;
}
__device__ __forceinline__ __half* hbufsel(int id) {
    if (id == ID_XLH) return g_xlh;
    return nullptr;
}

__device__ __forceinline__ void mma16(float* c, const uint32_t* a, const uint32_t* b) {
    asm volatile(
        "mma.sync.aligned.m16n8k16.row.col.f32.f16.f16.f32 "
        "{%0,%1,%2,%3}, {%4,%5,%6,%7}, {%8,%9}, {%0,%1,%2,%3};"
        : "+f"(c[0]), "+f"(c[1]), "+f"(c[2]), "+f"(c[3])
        : "r"(a[0]), "r"(a[1]), "r"(a[2]), "r"(a[3]), "r"(b[0]), "r"(b[1]));
}
__device__ __forceinline__ void ldsm4(uint32_t* r, uint32_t addr) {
    asm volatile("ldmatrix.sync.aligned.m8n8.x4.shared.b16 {%0,%1,%2,%3}, [%4];"
                 : "=r"(r[0]), "=r"(r[1]), "=r"(r[2]), "=r"(r[3]) : "r"(addr));
}

// ---------------- weight transpose to fp16 ----------------
__global__ void k_transposeh(const float* __restrict__ W, int K, int N, int Kpad, int dstoff) {
    int idx = blockIdx.x * blockDim.x + threadIdx.x;
    if (idx >= N * Kpad) return;
    int n = idx / Kpad, k = idx % Kpad;
    float v = (k < K) ? W[(size_t)k * N + n] : 0.f;
    g_wth[dstoff + idx] = __float2half_rn(v);
}

// ---------------- fp32-A fp16 GEMM (input projection only) ----------------
#define HSTRIDE 40
#define HA_B    (128 * HSTRIDE * 2)
#define HTILE_B (2 * HA_B)
__global__ void __launch_bounds__(256) k_hgemm(
        const float* __restrict__ Aext, int bt_off,
        const float* __restrict__ bias, int c_id,
        int M, int lda, int KS, int ldb, int ncout,
        float scale, int act, int mirror) {
    extern __shared__ char smc[];
    const float* A = Aext;
    const __half* Wt = g_wth + bt_off;
    float* C = bufsel(c_id);

    int tid = threadIdx.x, lane = tid & 31, wid = tid >> 5;
    int wm = wid & 3, wn = wid >> 2;
    int m0 = blockIdx.y * 128;
    int n0g = blockIdx.x * 128;
    int arow = tid >> 1, ahalf = tid & 1;

    uint32_t sbase;
    asm("{ .reg .u64 t; cvta.to.shared.u64 t, %1; cvt.u32.u64 %0, t; }" : "=r"(sbase) : "l"(smc));

    float pre[16];
    auto loadA_regs = [&](int kc) {
        int gm = m0 + arow;
        int k0 = kc * 32 + ahalf * 16;
        if (gm < M) {
#pragma unroll
            for (int i = 0; i < 16; i++)
                pre[i] = (k0 + i < lda) ? A[(size_t)gm * lda + k0 + i] : 0.f;
        } else {
#pragma unroll
            for (int i = 0; i < 16; i++) pre[i] = 0.f;
        }
    };
    auto stsA = [&](int buf) {
        __half2* dst = (__half2*)(smc + buf * HTILE_B + (arow * HSTRIDE + ahalf * 16) * 2);
        uint32_t v[8];
#pragma unroll
        for (int i = 0; i < 8; i++) {
            __half2 p = __floats2half2_rn(pre[i * 2], pre[i * 2 + 1]);
            v[i] = *reinterpret_cast<uint32_t*>(&p);
        }
        *reinterpret_cast<uint4*>(dst)     = *reinterpret_cast<uint4*>(v);
        *reinterpret_cast<uint4*>(dst + 4) = *reinterpret_cast<uint4*>(v + 4);
    };
    auto loadB = [&](int kc, int buf) {
        uint32_t bb = sbase + buf * HTILE_B + HA_B;
#pragma unroll
        for (int j = 0; j < 2; j++) {
            int flat = tid + j * 256;
            int n = flat >> 2, c8 = flat & 3;
            uint32_t dst = bb + (n * HSTRIDE + c8 * 8) * 2;
            const __half* src = Wt + (size_t)(n0g + n) * ldb + kc * 32 + c8 * 8;
            asm volatile("cp.async.cg.shared.global [%0], [%1], 16;" :: "r"(dst), "l"(src) : "memory");
        }
    };

    float acc[2][8][4];
#pragma unroll
    for (int mi = 0; mi < 2; mi++)
#pragma unroll
        for (int ni = 0; ni < 8; ni++)
#pragma unroll
            for (int e = 0; e < 4; e++) acc[mi][ni][e] = 0.f;

    loadA_regs(0); loadB(0, 0); stsA(0);
    asm volatile("cp.async.commit_group;\n\tcp.async.wait_group 0;" ::: "memory");
    __syncthreads();

    int lr8 = (lane & 7) + ((lane >> 3) & 1) * 8;
    int lk8 = (lane >> 4) * 8;

    for (int kc = 0; kc < KS; kc++) {
        int cur = kc & 1, nxt = 1 - cur;
        if (kc + 1 < KS) {
            loadA_regs(kc + 1); loadB(kc + 1, nxt);
            asm volatile("cp.async.commit_group;" ::: "memory");
        }
        uint32_t abase = sbase + cur * HTILE_B;
        uint32_t bbase = abase + HA_B;
#pragma unroll
        for (int h = 0; h < 2; h++) {
            uint32_t af[2][4];
#pragma unroll
            for (int mi = 0; mi < 2; mi++)
                ldsm4(af[mi], abase + (((wm * 32 + mi * 16) + lr8) * HSTRIDE + h * 16 + lk8) * 2);
            uint32_t bf[8][2];
#pragma unroll
            for (int nb = 0; nb < 4; nb++) {
                uint32_t q[4];
                ldsm4(q, bbase + (((wn * 64 + nb * 16) + lr8) * HSTRIDE + h * 16 + lk8) * 2);
                bf[nb * 2 + 0][0] = q[0]; bf[nb * 2 + 0][1] = q[2];
                bf[nb * 2 + 1][0] = q[1]; bf[nb * 2 + 1][1] = q[3];
            }
#pragma unroll
            for (int mi = 0; mi < 2; mi++)
#pragma unroll
                for (int ni = 0; ni < 8; ni++)
                    mma16(acc[mi][ni], af[mi], bf[ni]);
        }
        if (kc + 1 < KS) {
            stsA(nxt);
            asm volatile("cp.async.wait_group 0;" ::: "memory");
            __syncthreads();
        }
    }

    int lq = lane >> 2, lr = lane & 3;
#pragma unroll
    for (int mi = 0; mi < 2; mi++) {
#pragma unroll
        for (int half = 0; half < 2; half++) {
            int gr = m0 + wm * 32 + mi * 16 + lq + half * 8;
            if (gr >= M) continue;
#pragma unroll
            for (int ni = 0; ni < 8; ni++) {
                int gc = n0g + wn * 64 + ni * 8 + 2 * lr;
                float v0 = acc[mi][ni][half * 2 + 0];
                float v1 = acc[mi][ni][half * 2 + 1];
                if (bias) { v0 += __ldg(&bias[gc]); v1 += __ldg(&bias[gc + 1]); }
                v0 *= scale; v1 *= scale;
                if (act == 1) { v0 = v0 > 0.f ? v0 : 0.f; v1 = v1 > 0.f ? v1 : 0.f; }
                else if (act == 2) {
                    v0 = v0 > 0.f ? v0 : expm1f(v0);
                    v1 = v1 > 0.f ? v1 : expm1f(v1);
                }
                *reinterpret_cast<float2*>(C + (size_t)gr * ncout + gc) = make_float2(v0, v1);
                if (mirror)
                    *reinterpret_cast<__half2*>(g_hh + (size_t)gr * ncout + gc) =
                        __floats2half2_rn(v0, v1);
            }
        }
    }
}

// ---------------- fp16-A fp16 GEMM (A = g_hh, cp.async all the way) ----------------
template<int TN>
__global__ void __launch_bounds__(TN == 256 ? 512 : 256) k_h2gemm(
        int bt_off, const float* __restrict__ bias,
        int d1, int h1, int d2, int M, int KS, int ncout, int split,
        float scale, int act) {
    extern __shared__ char smc[];
    const int T = (TN == 256) ? 512 : 256;
    const int TILE = 10240 + TN * 80;
    const __half* Wt = g_wth + bt_off;
    float*  C1f = bufsel(d1);
    __half* C1h = hbufsel(d1);
    float*  C2f = bufsel(d2);

    int tid = threadIdx.x, lane = tid & 31, wid = tid >> 5;
    int wm = wid & 3, wn = wid >> 2;
    int m0 = blockIdx.y * 128;
    int n0g = blockIdx.x * TN;
    const int ldb = KS * 32;

    uint32_t sbase;
    asm("{ .reg .u64 t; cvta.to.shared.u64 t, %1; cvt.u32.u64 %0, t; }" : "=r"(sbase) : "l"(smc));

    auto loadA = [&](int kc, int buf) {
#pragma unroll
        for (int j = 0; j < 512 / T; j++) {
            int flat = tid + j * T;
            int row = flat >> 2, c8 = flat & 3;
            uint32_t dst = sbase + buf * TILE + (row * HSTRIDE + c8 * 8) * 2;
            const __half* src = g_hh + (size_t)(m0 + row) * HID + kc * 32 + c8 * 8;
            int sz = (m0 + row < M) ? 16 : 0;
            asm volatile("cp.async.cg.shared.global [%0], [%1], 16, %2;"
                         :: "r"(dst), "l"(src), "r"(sz) : "memory");
        }
    };
    auto loadB = [&](int kc, int buf) {
        uint32_t bb = sbase + buf * TILE + 10240;
#pragma unroll
        for (int j = 0; j < TN * 4 / T; j++) {
            int flat = tid + j * T;
            int n = flat >> 2, c8 = flat & 3;
            uint32_t dst = bb + (n * HSTRIDE + c8 * 8) * 2;
            const __half* src = Wt + (size_t)(n0g + n) * ldb + kc * 32 + c8 * 8;
            asm volatile("cp.async.cg.shared.global [%0], [%1], 16;" :: "r"(dst), "l"(src) : "memory");
        }
    };

    float acc[2][8][4];
#pragma unroll
    for (int mi = 0; mi < 2; mi++)
#pragma unroll
        for (int ni = 0; ni < 8; ni++)
#pragma unroll
            for (int e = 0; e < 4; e++) acc[mi][ni][e] = 0.f;

    loadA(0, 0); loadB(0, 0);
    asm volatile("cp.async.commit_group;\n\tcp.async.wait_group 0;" ::: "memory");
    __syncthreads();

    int lr8 = (lane & 7) + ((lane >> 3) & 1) * 8;
    int lk8 = (lane >> 4) * 8;

    for (int kc = 0; kc < KS; kc++) {
        int cur = kc & 1, nxt = 1 - cur;
        if (kc + 1 < KS) {
            loadA(kc + 1, nxt); loadB(kc + 1, nxt);
            asm volatile("cp.async.commit_group;" ::: "memory");
        }
        uint32_t abase = sbase + cur * TILE;
        uint32_t bbase = abase + 10240;
#pragma unroll
        for (int h = 0; h < 2; h++) {
            uint32_t af[2][4];
#pragma unroll
            for (int mi = 0; mi < 2; mi++)
                ldsm4(af[mi], abase + (((wm * 32 + mi * 16) + lr8) * HSTRIDE + h * 16 + lk8) * 2);
            uint32_t bf[8][2];
#pragma unroll
            for (int nb = 0; nb < 4; nb++) {
                uint32_t q[4];
                ldsm4(q, bbase + (((wn * 64 + nb * 16) + lr8) * HSTRIDE + h * 16 + lk8) * 2);
                bf[nb * 2 + 0][0] = q[0]; bf[nb * 2 + 0][1] = q[2];
                bf[nb * 2 + 1][0] = q[1]; bf[nb * 2 + 1][1] = q[3];
            }
#pragma unroll
            for (int mi = 0; mi < 2; mi++)
#pragma unroll
                for (int ni = 0; ni < 8; ni++)
                    mma16(acc[mi][ni], af[mi], bf[ni]);
        }
        if (kc + 1 < KS) {
            asm volatile("cp.async.wait_group 0;" ::: "memory");
            __syncthreads();
        }
    }

    int lq = lane >> 2, lr = lane & 3;
#pragma unroll
    for (int mi = 0; mi < 2; mi++) {
#pragma unroll
        for (int half = 0; half < 2; half++) {
            int gr = m0 + wm * 32 + mi * 16 + lq + half * 8;
            if (gr >= M) continue;
#pragma unroll
            for (int ni = 0; ni < 8; ni++) {
                int gc = n0g + wn * 64 + ni * 8 + 2 * lr;
                float v0 = acc[mi][ni][half * 2 + 0];
                float v1 = acc[mi][ni][half * 2 + 1];
                if (bias) { v0 += __ldg(&bias[gc]); v1 += __ldg(&bias[gc + 1]); }
                v0 *= scale; v1 *= scale;
                if (act == 1) { v0 = v0 > 0.f ? v0 : 0.f; v1 = v1 > 0.f ? v1 : 0.f; }
                if (gc < split) {
                    if (h1)
                        *reinterpret_cast<__half2*>(C1h + (size_t)gr * ncout + gc) =
                            __floats2half2_rn(v0, v1);
                    else
                        *reinterpret_cast<float2*>(C1f + (size_t)gr * ncout + gc) = make_float2(v0, v1);
                } else {
                    *reinterpret_cast<float2*>(C2f + (size_t)gr * ncout + gc - split) = make_float2(v0, v1);
                }
            }
        }
    }
}

// ---------------- CSR build ----------------
__global__ void k_deg_init() {
    int i = blockIdx.x * blockDim.x + threadIdx.x;
    if (i <= NN) g_rowptr[i] = (i == 0) ? 0 : 1;
}
__global__ void k_deg_count(const int* __restrict__ ei) {
    int e = blockIdx.x * blockDim.x + threadIdx.x;
    if (e < EE) atomicAdd(&g_rowptr[ei[EE + e] + 1], 1);
}
#define SCB 256
__global__ void k_scan1() {
    __shared__ int s[SCB];
    int i = blockIdx.x * SCB + threadIdx.x;
    int v = (i < NN) ? g_rowptr[1 + i] : 0;
    s[threadIdx.x] = v;
    __syncthreads();
#pragma unroll
    for (int off = 1; off < SCB; off <<= 1) {
        int t = 0;
        if ((int)threadIdx.x >= off) t = s[threadIdx.x - off];
        __syncthreads();
        if ((int)threadIdx.x >= off) s[threadIdx.x] += t;
        __syncthreads();
    }
    if (i < NN) g_rowptr[1 + i] = s[threadIdx.x];
    if (threadIdx.x == SCB - 1) g_bsum[blockIdx.x] = s[threadIdx.x];
}
__global__ void k_scan2(int nb) {
    __shared__ int s[512];
    int v = ((int)threadIdx.x < nb) ? g_bsum[threadIdx.x] : 0;
    s[threadIdx.x] = v;
    __syncthreads();
#pragma unroll
    for (int off = 1; off < 512; off <<= 1) {
        int t = 0;
        if ((int)threadIdx.x >= off) t = s[threadIdx.x - off];
        __syncthreads();
        if ((int)threadIdx.x >= off) s[threadIdx.x] += t;
        __syncthreads();
    }
    if ((int)threadIdx.x < nb) g_bsum[threadIdx.x] = s[threadIdx.x];
}
__global__ void k_scan3() {
    int i = blockIdx.x * SCB + threadIdx.x;
    if (blockIdx.x > 0 && i < NN) g_rowptr[1 + i] += g_bsum[blockIdx.x - 1];
}
__global__ void k_cursor_init() {
    int i = blockIdx.x * blockDim.x + threadIdx.x;
    if (i < NN) g_cursor[i] = g_rowptr[i];
}
__global__ void k_scatter(const int* __restrict__ ei) {
    int idx = blockIdx.x * blockDim.x + threadIdx.x;
    if (idx >= TOTE) return;
    int tgt = (idx < EE) ? ei[EE + idx] : (idx - EE);
    int pos = atomicAdd(&g_cursor[tgt], 1);
    g_eidx[pos] = idx;
}

// ---------------- edge_attr mean ----------------
__global__ void k_zero_small() {
    int i = threadIdx.x;
    if (i < EDD) g_meansum[i] = 0.f;
}
__global__ void k_mean(const float* __restrict__ ea) {
    float loc[EDD];
#pragma unroll
    for (int k = 0; k < EDD; k++) loc[k] = 0.f;
    for (int e = blockIdx.x * blockDim.x + threadIdx.x; e < EE; e += gridDim.x * blockDim.x) {
#pragma unroll
        for (int k = 0; k < EDD; k++) loc[k] += ea[(size_t)e * EDD + k];
    }
#pragma unroll
    for (int k = 0; k < EDD; k++) {
        float v = loc[k];
#pragma unroll
        for (int o = 16; o; o >>= 1) v += __shfl_xor_sync(0xffffffffu, v, o);
        if ((threadIdx.x & 31) == 0) atomicAdd(&g_meansum[k], v);
    }
}
__global__ void k_epself(const float* __restrict__ We) {
    int j = threadIdx.x;
    const float invE = 1.f / (float)EE;
    float s = 0.f;
#pragma unroll
    for (int k = 0; k < EDD; k++) s += g_meansum[k] * invE * We[k * HID + j];
    g_epself[j] = s;
}

// ---------------- fused GAT layer (fp16 xl gather, half-warp head ownership) ----------------
__global__ void __launch_bounds__(256) k_gat(const int* __restrict__ ei,
                                             const float* __restrict__ ea,
                                             const float* __restrict__ We,
                                             const float* __restrict__ att,
                                             const float* __restrict__ bgat) {
    __shared__ float sWe[EDD * HID];
    __shared__ float satt[HID];
    __shared__ float sep[HID];
    __shared__ float sbg[HID];
    for (int i = threadIdx.x; i < EDD * HID; i += blockDim.x) sWe[i] = We[i];
    for (int i = threadIdx.x; i < HID; i += blockDim.x) {
        satt[i] = att[i]; sep[i] = g_epself[i]; sbg[i] = bgat[i];
    }
    __syncthreads();
    const float2* sWe2  = (const float2*)sWe;
    const float2* satt2 = (const float2*)satt;
    const float2* sep2  = (const float2*)sep;
    const float2* sbg2  = (const float2*)sbg;

    int lane = threadIdx.x & 31;
    int half16 = lane >> 4;                 // this lane's head parity
    int gw = (blockIdx.x * blockDim.x + threadIdx.x) >> 5;
    int nwarps = (gridDim.x * blockDim.x) >> 5;

    for (int t = gw; t < NN; t += nwarps) {
        int r0 = g_rowptr[t], r1 = g_rowptr[t + 1];
        const float2* xr2p = (const float2*)(g_xr + (size_t)t * HID);
        float2 xr2[4];
#pragma unroll
        for (int q = 0; q < 4; q++) xr2[q] = xr2p[q * 32 + lane];

        float mxq[4];
#pragma unroll
        for (int q = 0; q < 4; q++) mxq[q] = -1e30f;

        // pass 1: logits + per-head max
        for (int p = r0; p < r1; p++) {
            int e = g_eidx[p];
            bool slf = (e >= EE);
            int src;
            float w[EDD];
            if (slf) src = e - EE;
            else {
                src = ei[e];
                float eav = (lane < EDD) ? ea[(size_t)e * EDD + lane] : 0.f;
#pragma unroll
                for (int k = 0; k < EDD; k++) w[k] = __shfl_sync(0xffffffffu, eav, k);
            }
            const __half2* xl2 = (const __half2*)(g_xlh + (size_t)src * HID);
            float lgq[4];
#pragma unroll
            for (int q = 0; q < 4; q++) {
                int idx = q * 32 + lane;
                float2 xl = __half22float2(xl2[idx]);
                float2 ep;
                if (slf) ep = sep2[idx];
                else {
                    ep = make_float2(0.f, 0.f);
#pragma unroll
                    for (int k = 0; k < EDD; k++) {
                        float2 wv = sWe2[k * 128 + idx];
                        ep.x += w[k] * wv.x; ep.y += w[k] * wv.y;
                    }
                }
                float sx = xl.x + xr2[q].x + ep.x;
                float sy = xl.y + xr2[q].y + ep.y;
                sx = sx > 0.f ? sx : NEG_SLOPE * sx;
                sy = sy > 0.f ? sy : NEG_SLOPE * sy;
                float2 at = satt2[idx];
                lgq[q] = sx * at.x + sy * at.y;
            }
#pragma unroll
            for (int o = 1; o < 16; o <<= 1)
#pragma unroll
                for (int q = 0; q < 4; q++) lgq[q] += __shfl_xor_sync(0xffffffffu, lgq[q], o);
#pragma unroll
            for (int q = 0; q < 4; q++) mxq[q] = fmaxf(mxq[q], lgq[q]);
            if ((lane & 15) == 0) {
#pragma unroll
                for (int q = 0; q < 4; q++) g_elog[(size_t)p * NH + 2 * q + half16] = lgq[q];
            }
        }

        // pass 2: denominator + unnormalized weighted sum
        float denq[4];
        float2 acc2[4];
#pragma unroll
        for (int q = 0; q < 4; q++) { denq[q] = 0.f; acc2[q] = make_float2(0.f, 0.f); }
        for (int p = r0; p < r1; p++) {
            int e = g_eidx[p];
            int src = (e >= EE) ? (e - EE) : ei[e];
            const __half2* xl2 = (const __half2*)(g_xlh + (size_t)src * HID);
#pragma unroll
            for (int q = 0; q < 4; q++) {
                float lg = g_elog[(size_t)p * NH + 2 * q + half16];
                float ex = __expf(lg - mxq[q]);
                denq[q] += ex;
                float2 xl = __half22float2(xl2[q * 32 + lane]);
                acc2[q].x += ex * xl.x;
                acc2[q].y += ex * xl.y;
            }
        }
#pragma unroll
        for (int q = 0; q < 4; q++) {
            int idx = q * 32 + lane;
            float inv = 1.f / (denq[q] + 1e-16f);
            float2 bg = sbg2[idx];
            float v0 = (acc2[q].x * inv + bg.x) * BN_SCALE;
            float v1 = (acc2[q].y * inv + bg.y) * BN_SCALE;
            v0 = v0 > 0.f ? v0 : expm1f(v0);
            v1 = v1 > 0.f ? v1 : expm1f(v1);
            float2* hp = (float2*)(g_h + (size_t)t * HID) + idx;
            float2 hv = *hp;
            hv.x += v0; hv.y += v1;
            *hp = hv;
            *((__half2*)(g_hh + (size_t)t * HID) + idx) = __floats2half2_rn(hv.x, hv.y);
        }
    }
}

// ---------------- SIMT GEMM (small readout mats) ----------------
__global__ void k_gemm(int a_id, const float* __restrict__ B, const float* __restrict__ bias,
                       int c_id, int M, int K, int Nc, float scale, int act) {
    __shared__ float As[16][65];
    __shared__ float Bs[16][65];
    const float* A = bufsel(a_id);
    float* Cp = bufsel(c_id);

    int t = threadIdx.x;
    int tx = t & 15, ty = t >> 4;
    int n0 = blockIdx.x * 64, m0 = blockIdx.y * 64;
    float acc[4][4] = {};

    for (int kk = 0; kk < K; kk += 16) {
#pragma unroll
        for (int j = 0; j < 4; j++) {
            int idx = t + j * 256;
            int m = idx >> 4, k = idx & 15;
            int gm = m0 + m, gk = kk + k;
            As[k][m] = (gm < M && gk < K) ? A[(size_t)gm * K + gk] : 0.f;
        }
#pragma unroll
        for (int j = 0; j < 4; j++) {
            int idx = t + j * 256;
            int k = idx >> 6, n = idx & 63;
            int gk = kk + k;
            Bs[k][n] = (gk < K) ? B[(size_t)gk * Nc + n0 + n] : 0.f;
        }
        __syncthreads();
#pragma unroll
        for (int k = 0; k < 16; k++) {
            float a[4], b[4];
#pragma unroll
            for (int i = 0; i < 4; i++) a[i] = As[k][ty + 16 * i];
#pragma unroll
            for (int j = 0; j < 4; j++) b[j] = Bs[k][tx + 16 * j];
#pragma unroll
            for (int i = 0; i < 4; i++)
#pragma unroll
                for (int j = 0; j < 4; j++) acc[i][j] += a[i] * b[j];
        }
        __syncthreads();
    }
#pragma unroll
    for (int i = 0; i < 4; i++) {
        int gm = m0 + ty + 16 * i;
        if (gm >= M) continue;
#pragma unroll
        for (int j = 0; j < 4; j++) {
            int gn = n0 + tx + 16 * j;
            float v = acc[i][j];
            if (bias) v += bias[gn];
            v *= scale;
            if (act == 1) v = v > 0.f ? v : 0.f;
            else if (act == 2) v = v > 0.f ? v : expm1f(v);
            Cp[(size_t)gm * Nc + gn] = v;
        }
    }
}

// ---------------- gate dot ----------------
__global__ void k_gatedot(const float* __restrict__ Wg2, const float* __restrict__ bg2) {
    int lane = threadIdx.x & 31;
    int warp = (blockIdx.x * blockDim.x + threadIdx.x) >> 5;
    if (warp >= NN) return;
    float s = 0.f;
#pragma unroll
    for (int j = lane; j < 128; j += 32) s += g_g1[(size_t)warp * 128 + j] * Wg2[j];
#pragma unroll
    for (int o = 16; o; o >>= 1) s += __shfl_xor_sync(0xffffffffu, s, o);
    if (lane == 0) g_gate[warp] = s + bg2[0];
}

// ---------------- fused pooling ----------------
__global__ void __launch_bounds__(256) k_poolf(const int* __restrict__ batch) {
    int lane = threadIdx.x & 31;
    int b = (blockIdx.x * blockDim.x + threadIdx.x) >> 5;
    if (b >= BB) return;

    int s0, s1;
    if (lane == 0) {
        int lo = 0, hi = NN;
        while (lo < hi) { int m = (lo + hi) >> 1; if (batch[m] < b) lo = m + 1; else hi = m; }
        s0 = lo;
        lo = s0; hi = NN;
        while (lo < hi) { int m = (lo + hi) >> 1; if (batch[m] < b + 1) lo = m + 1; else hi = m; }
        s1 = lo;
    }
    s0 = __shfl_sync(0xffffffffu, s0, 0);
    s1 = __shfl_sync(0xffffffffu, s1, 0);

    float mx = -1e30f;
    for (int n = s0 + lane; n < s1; n += 32) mx = fmaxf(mx, g_gate[n]);
#pragma unroll
    for (int o = 16; o; o >>= 1) mx = fmaxf(mx, __shfl_xor_sync(0xffffffffu, mx, o));

    float den = 0.f;
    float acc[8];
#pragma unroll
    for (int j = 0; j < 8; j++) acc[j] = 0.f;
    for (int n = s0; n < s1; n++) {
        float ex = __expf(g_gate[n] - mx);
        den += ex;
        const float* hr = g_h + (size_t)n * HID;
#pragma unroll
        for (int j = 0; j < 8; j++) acc[j] += ex * hr[j * 32 + lane];
    }
    float inv = 1.f / (den + 1e-16f);
#pragma unroll
    for (int j = 0; j < 8; j++)
        g_pooled[(size_t)b * HID + j * 32 + lane] = acc[j] * inv;
}

__global__ void k_final(const float* __restrict__ W4, const float* __restrict__ b4,
                        float* __restrict__ out) {
    int b = blockIdx.x * blockDim.x + threadIdx.x;
    if (b >= BB) return;
    float s = b4[0];
#pragma unroll
    for (int k = 0; k < 64; k++) s += g_r3[b * 64 + k] * W4[k];
    out[b] = s;
}

// ---------------- host orchestration ----------------
extern "C" void kernel_launch(void* const* d_in, const int* in_sizes, int n_in,
                              void* d_out, int out_size) {
    const float* x     = (const float*)d_in[0];
    const int*   ei    = (const int*)  d_in[1];
    const float* ea    = (const float*)d_in[2];
    const int*   batch = (const int*)  d_in[3];
    const float* W_in  = (const float*)d_in[4];
    const float* b_in  = (const float*)d_in[5];
    const float* Wl    = (const float*)d_in[6];
    const float* Wr    = (const float*)d_in[7];
    const float* We    = (const float*)d_in[8];
    const float* att   = (const float*)d_in[9];
    const float* b_gat = (const float*)d_in[10];
    const float* Wg1   = (const float*)d_in[11];
    const float* bg1   = (const float*)d_in[12];
    const float* Wg2   = (const float*)d_in[13];
    const float* bg2   = (const float*)d_in[14];
    const float* W1    = (const float*)d_in[15];
    const float* b1    = (const float*)d_in[16];
    const float* W2    = (const float*)d_in[17];
    const float* b2    = (const float*)d_in[18];
    const float* W3    = (const float*)d_in[19];
    const float* b3    = (const float*)d_in[20];
    const float* W4    = (const float*)d_in[21];
    const float* b4    = (const float*)d_in[22];
    float* out = (float*)d_out;

    const int SMEMH   = 2 * HTILE_B;              // 40960 (input proj)
    const int SMEM256 = 2 * (10240 + 256 * 80);   // 61440
    const int SMEM128 = 2 * (10240 + 128 * 80);   // 40960
    cudaFuncSetAttribute(k_hgemm, cudaFuncAttributeMaxDynamicSharedMemorySize, SMEMH);
    cudaFuncSetAttribute(k_h2gemm<256>, cudaFuncAttributeMaxDynamicSharedMemorySize, SMEM256);
    cudaFuncSetAttribute(k_h2gemm<128>, cudaFuncAttributeMaxDynamicSharedMemorySize, SMEM128);

    const int MTB = (NN + 127) / 128;  // 782
    const int SCANB = (NN + SCB - 1) / SCB;
    dim3 thr(256);

    // fp16 transposed weights
    k_transposeh<<<(256 * 96 + 255) / 256, 256>>>(W_in, IND, HID, 96, WTH_WIN);
    for (int i = 0; i < NL; i++) {
        k_transposeh<<<(256 * 256 + 255) / 256, 256>>>(Wl + (size_t)i * 65536, HID, HID, 256, WTH_WLR(i));
        k_transposeh<<<(256 * 256 + 255) / 256, 256>>>(Wr + (size_t)i * 65536, HID, HID, 256, WTH_WLR(i) + 65536);
    }
    k_transposeh<<<(128 * 256 + 255) / 256, 256>>>(Wg1, HID, 128, 256, WTH_WG1);

    // CSR over targets
    k_deg_init<<<(NN + 256) / 256, thr>>>();
    k_deg_count<<<(EE + 255) / 256, thr>>>(ei);
    k_scan1<<<SCANB, SCB>>>();
    k_scan2<<<1, 512>>>(SCANB);
    k_scan3<<<SCANB, SCB>>>();
    k_cursor_init<<<(NN + 255) / 256, thr>>>();
    k_scatter<<<(TOTE + 255) / 256, thr>>>(ei);

    // edge_attr mean
    k_zero_small<<<1, 32>>>();
    k_mean<<<256, 256>>>(ea);

    // input projection (fp32 A) with fp16 mirror
    k_hgemm<<<dim3(2, MTB), thr, SMEMH>>>(x, WTH_WIN, b_in, ID_H,
                                          NN, IND, 3, 96, 256, BN_SCALE, 2, 1);

    for (int i = 0; i < NL; i++) {
        const float* Wei = We + (size_t)i * EDD * HID;
        const float* ati = att + (size_t)i * NH * CC;
        const float* bgi = b_gat + (size_t)i * HID;

        // fused xl|xr GEMM from fp16 mirror: N=512, 2 blocks of 256 cols
        k_h2gemm<256><<<dim3(2, MTB), 512, SMEM256>>>(WTH_WLR(i), nullptr,
                                                      ID_XLH, 1, ID_XR,
                                                      NN, 8, 256, 256, 1.f, 0);
        k_epself<<<1, HID>>>(Wei);
        k_gat<<<2048, thr>>>(ei, ea, Wei, ati, bgi);
    }

    // global attention pooling
    k_h2gemm<128><<<dim3(1, MTB), 256, SMEM128>>>(WTH_WG1, bg1, ID_G1, 0, ID_G1,
                                                  NN, 8, 128, 128, 1.f, 1);
    k_gatedot<<<(NN * 32 + 255) / 256, thr>>>(Wg2, bg2);
    k_poolf<<<(BB * 32 + 255) / 256, thr>>>(batch);

    // readout MLP
    k_gemm<<<dim3(256 / 64, BB / 64), thr>>>(ID_POOLED, W1, b1, ID_R1, BB, HID, 256, BN_SCALE, 1);
    k_gemm<<<dim3(128 / 64, BB / 64), thr>>>(ID_R1, W2, b2, ID_R2, BB, 256, 128, BN_SCALE, 1);
    k_gemm<<<dim3(64 / 64, BB / 64), thr>>>(ID_R2, W3, b3, ID_R3, BB, 128, 64, 1.f, 1);
    k_final<<<(BB + 255) / 256, thr>>>(W4, b4, out);
}